// round 1
// baseline (speedup 1.0000x reference)
#include <cuda_runtime.h>
#include <math.h>

#define B_  2
#define L_  2048
#define D_  2048
#define H_  16
#define DH  128
#define BH  (B_*H_)
#define NEGV  (-1000000000.0f)
#define SCALE 0.08838834764831845f

// ---------------- scratch (device globals; no runtime allocation) ----------
__device__ float g_Q[B_*H_*L_*DH];           // [B,H,L,Dh]
__device__ float g_K[B_*H_*L_*DH];
__device__ float g_V[B_*H_*L_*DH];
__device__ float g_S[(size_t)B_*H_*L_*L_];   // [B*H, L, L] scores -> probs
__device__ float g_Y[B_*L_*D_];              // [B,L,D] attention output

// =============== GEMM 1: qkv = x @ w_qkv, scatter into Q/K/V ==============
// C[4096,6144] = A[4096,2048] * B[2048,6144], 128x128 tile, 8x8 micro.
__global__ __launch_bounds__(256) void k_qkv(const float* __restrict__ A,
                                             const float* __restrict__ Bw) {
    __shared__ float As[8][128];
    __shared__ float Bs[8][128];
    const int tid = threadIdx.x;
    const int bn = blockIdx.x, bm = blockIdx.y;
    const int tx = tid & 15, ty = tid >> 4;
    const int lm = tid >> 1, lk = (tid & 1) * 4;
    const int K = 2048, N = 3 * D_;
    const float* Ap = A + (size_t)(bm * 128 + lm) * K + lk;
    const float* Bp = Bw + (size_t)(tid >> 5) * N + bn * 128 + (tid & 31) * 4;

    float acc[8][8];
#pragma unroll
    for (int i = 0; i < 8; i++)
#pragma unroll
        for (int j = 0; j < 8; j++) acc[i][j] = 0.f;

    for (int kp = 0; kp < K; kp += 8) {
        float4 a  = *(const float4*)(Ap + kp);
        float4 bl = *(const float4*)(Bp + (size_t)kp * N);
        __syncthreads();
        As[lk + 0][lm] = a.x; As[lk + 1][lm] = a.y;
        As[lk + 2][lm] = a.z; As[lk + 3][lm] = a.w;
        *(float4*)&Bs[tid >> 5][(tid & 31) * 4] = bl;
        __syncthreads();
#pragma unroll
        for (int kk = 0; kk < 8; kk++) {
            float av[8], bv[8];
            *(float4*)(av)     = *(const float4*)&As[kk][ty * 8];
            *(float4*)(av + 4) = *(const float4*)&As[kk][ty * 8 + 4];
            *(float4*)(bv)     = *(const float4*)&Bs[kk][tx * 8];
            *(float4*)(bv + 4) = *(const float4*)&Bs[kk][tx * 8 + 4];
#pragma unroll
            for (int i = 0; i < 8; i++)
#pragma unroll
                for (int j = 0; j < 8; j++)
                    acc[i][j] = fmaf(av[i], bv[j], acc[i][j]);
        }
    }
#pragma unroll
    for (int i = 0; i < 8; i++) {
        int m = bm * 128 + ty * 8 + i;
        int bb = m >> 11, l = m & 2047;
#pragma unroll
        for (int j = 0; j < 8; j++) {
            int n = bn * 128 + tx * 8 + j;
            int part = n >> 11, idx = n & 2047;
            int h = idx >> 7, d = idx & 127;
            float* dst = (part == 0) ? g_Q : ((part == 1) ? g_K : g_V);
            dst[((bb * H_ + h) * L_ + l) * DH + d] = acc[i][j];
        }
    }
}

// ======================= RoPE on Q and K, in place ========================
__global__ void k_rope() {
    int idx = blockIdx.x * blockDim.x + threadIdx.x;   // B*H*L*64 threads
    int i   = idx & 63;
    int bhl = idx >> 6;
    int l   = bhl & 2047;
    float inv_freq = powf(10000.0f, -(float)(2 * i) * (1.0f / 128.0f));
    float ang = (float)l * inv_freq;
    float s, c;
    sincosf(ang, &s, &c);
    int base = bhl << 7;
    float q0 = g_Q[base + i], q1 = g_Q[base + i + 64];
    g_Q[base + i]      = q0 * c - q1 * s;
    g_Q[base + i + 64] = q1 * c + q0 * s;
    float k0 = g_K[base + i], k1 = g_K[base + i + 64];
    g_K[base + i]      = k0 * c - k1 * s;
    g_K[base + i + 64] = k1 * c + k0 * s;
}

// ============= GEMM 2: S = Q @ K^T * scale, causal + pad mask =============
__global__ __launch_bounds__(256) void k_scores(const int* __restrict__ amask) {
    __shared__ float As[8][128];
    __shared__ float Bs[8][128];
    const int tid = threadIdx.x;
    const int bn = blockIdx.x, bm = blockIdx.y, bh = blockIdx.z;
    const int tx = tid & 15, ty = tid >> 4;
    const int lm = tid >> 1, lk = (tid & 1) * 4;
    const int bb = bh >> 4;
    const float* Qp = g_Q + (size_t)bh * L_ * DH + (size_t)(bm * 128 + lm) * DH + lk;
    const float* Kp = g_K + (size_t)bh * L_ * DH + (size_t)(bn * 128 + lm) * DH + lk;

    float acc[8][8];
#pragma unroll
    for (int i = 0; i < 8; i++)
#pragma unroll
        for (int j = 0; j < 8; j++) acc[i][j] = 0.f;

    if (bn <= bm) {  // skip fully-masked tiles above the diagonal
        for (int kp = 0; kp < DH; kp += 8) {
            float4 a  = *(const float4*)(Qp + kp);
            float4 bl = *(const float4*)(Kp + kp);
            __syncthreads();
            As[lk + 0][lm] = a.x;  As[lk + 1][lm] = a.y;
            As[lk + 2][lm] = a.z;  As[lk + 3][lm] = a.w;
            Bs[lk + 0][lm] = bl.x; Bs[lk + 1][lm] = bl.y;
            Bs[lk + 2][lm] = bl.z; Bs[lk + 3][lm] = bl.w;
            __syncthreads();
#pragma unroll
            for (int kk = 0; kk < 8; kk++) {
                float av[8], bv[8];
                *(float4*)(av)     = *(const float4*)&As[kk][ty * 8];
                *(float4*)(av + 4) = *(const float4*)&As[kk][ty * 8 + 4];
                *(float4*)(bv)     = *(const float4*)&Bs[kk][tx * 8];
                *(float4*)(bv + 4) = *(const float4*)&Bs[kk][tx * 8 + 4];
#pragma unroll
                for (int i = 0; i < 8; i++)
#pragma unroll
                    for (int j = 0; j < 8; j++)
                        acc[i][j] = fmaf(av[i], bv[j], acc[i][j]);
            }
        }
    }
    float* Sp = g_S + (size_t)bh * L_ * L_;
#pragma unroll
    for (int i = 0; i < 8; i++) {
        int q = bm * 128 + ty * 8 + i;
#pragma unroll
        for (int j = 0; j < 8; j++) {
            int kc = bn * 128 + tx * 8 + j;
            bool valid = (kc <= q) && (amask[bb * L_ + kc] != 0);
            Sp[(size_t)q * L_ + kc] = valid ? acc[i][j] * SCALE : NEGV;
        }
    }
}

// ============================ row softmax =================================
__global__ __launch_bounds__(256) void k_softmax() {
    __shared__ float red[256];
    float* row = g_S + (size_t)blockIdx.x * L_;
    int t = threadIdx.x;
    float v[8];
    float mx = -3.4e38f;
#pragma unroll
    for (int i = 0; i < 8; i++) { v[i] = row[t + 256 * i]; mx = fmaxf(mx, v[i]); }
    red[t] = mx; __syncthreads();
    for (int s = 128; s > 0; s >>= 1) {
        if (t < s) red[t] = fmaxf(red[t], red[t + s]);
        __syncthreads();
    }
    mx = red[0];
    __syncthreads();
    float sum = 0.f;
#pragma unroll
    for (int i = 0; i < 8; i++) { v[i] = expf(v[i] - mx); sum += v[i]; }
    red[t] = sum; __syncthreads();
    for (int s = 128; s > 0; s >>= 1) {
        if (t < s) red[t] += red[t + s];
        __syncthreads();
    }
    float inv = 1.0f / red[0];
#pragma unroll
    for (int i = 0; i < 8; i++) row[t + 256 * i] = v[i] * inv;
}

// ============== GEMM 3: Y = P @ V, scatter to [B,L,D] =====================
__global__ __launch_bounds__(256) void k_pv() {
    __shared__ float As[8][128];
    __shared__ float Bs[8][128];
    const int tid = threadIdx.x;
    const int bm = blockIdx.y, bh = blockIdx.z;
    const int tx = tid & 15, ty = tid >> 4;
    const int lm = tid >> 1, lk = (tid & 1) * 4;
    const float* Pp = g_S + (size_t)bh * L_ * L_ + (size_t)(bm * 128 + lm) * L_ + lk;
    const float* Vp = g_V + (size_t)bh * L_ * DH + (size_t)(tid >> 5) * DH + (tid & 31) * 4;

    float acc[8][8];
#pragma unroll
    for (int i = 0; i < 8; i++)
#pragma unroll
        for (int j = 0; j < 8; j++) acc[i][j] = 0.f;

    const int kmax = (bm + 1) * 128;   // causal: P is exactly 0 beyond this
    for (int kp = 0; kp < kmax; kp += 8) {
        float4 a  = *(const float4*)(Pp + kp);
        float4 bl = *(const float4*)(Vp + (size_t)kp * DH);
        __syncthreads();
        As[lk + 0][lm] = a.x; As[lk + 1][lm] = a.y;
        As[lk + 2][lm] = a.z; As[lk + 3][lm] = a.w;
        *(float4*)&Bs[tid >> 5][(tid & 31) * 4] = bl;
        __syncthreads();
#pragma unroll
        for (int kk = 0; kk < 8; kk++) {
            float av[8], bv[8];
            *(float4*)(av)     = *(const float4*)&As[kk][ty * 8];
            *(float4*)(av + 4) = *(const float4*)&As[kk][ty * 8 + 4];
            *(float4*)(bv)     = *(const float4*)&Bs[kk][tx * 8];
            *(float4*)(bv + 4) = *(const float4*)&Bs[kk][tx * 8 + 4];
#pragma unroll
            for (int i = 0; i < 8; i++)
#pragma unroll
                for (int j = 0; j < 8; j++)
                    acc[i][j] = fmaf(av[i], bv[j], acc[i][j]);
        }
    }
    const int bb = bh >> 4, h = bh & 15;
#pragma unroll
    for (int i = 0; i < 8; i++) {
        int l = bm * 128 + ty * 8 + i;
#pragma unroll
        for (int j = 0; j < 8; j++) {
            int d = tx * 8 + j;
            g_Y[(size_t)(bb * L_ + l) * D_ + h * DH + d] = acc[i][j];
        }
    }
}

// ================= GEMM 4: out = Y @ w_proj ===============================
__global__ __launch_bounds__(256) void k_proj(const float* __restrict__ Bw,
                                              float* __restrict__ out) {
    __shared__ float As[8][128];
    __shared__ float Bs[8][128];
    const int tid = threadIdx.x;
    const int bn = blockIdx.x, bm = blockIdx.y;
    const int tx = tid & 15, ty = tid >> 4;
    const int lm = tid >> 1, lk = (tid & 1) * 4;
    const int K = 2048, N = D_;
    const float* Ap = g_Y + (size_t)(bm * 128 + lm) * K + lk;
    const float* Bp = Bw + (size_t)(tid >> 5) * N + bn * 128 + (tid & 31) * 4;

    float acc[8][8];
#pragma unroll
    for (int i = 0; i < 8; i++)
#pragma unroll
        for (int j = 0; j < 8; j++) acc[i][j] = 0.f;

    for (int kp = 0; kp < K; kp += 8) {
        float4 a  = *(const float4*)(Ap + kp);
        float4 bl = *(const float4*)(Bp + (size_t)kp * N);
        __syncthreads();
        As[lk + 0][lm] = a.x; As[lk + 1][lm] = a.y;
        As[lk + 2][lm] = a.z; As[lk + 3][lm] = a.w;
        *(float4*)&Bs[tid >> 5][(tid & 31) * 4] = bl;
        __syncthreads();
#pragma unroll
        for (int kk = 0; kk < 8; kk++) {
            float av[8], bv[8];
            *(float4*)(av)     = *(const float4*)&As[kk][ty * 8];
            *(float4*)(av + 4) = *(const float4*)&As[kk][ty * 8 + 4];
            *(float4*)(bv)     = *(const float4*)&Bs[kk][tx * 8];
            *(float4*)(bv + 4) = *(const float4*)&Bs[kk][tx * 8 + 4];
#pragma unroll
            for (int i = 0; i < 8; i++)
#pragma unroll
                for (int j = 0; j < 8; j++)
                    acc[i][j] = fmaf(av[i], bv[j], acc[i][j]);
        }
    }
#pragma unroll
    for (int i = 0; i < 8; i++) {
        int m = bm * 128 + ty * 8 + i;
#pragma unroll
        for (int j = 0; j < 8; j++) {
            int n = bn * 128 + tx * 8 + j;
            out[(size_t)m * N + n] = acc[i][j];
        }
    }
}

// ============================== launcher ==================================
extern "C" void kernel_launch(void* const* d_in, const int* in_sizes, int n_in,
                              void* d_out, int out_size) {
    const float* x      = (const float*)d_in[0];
    const int*   amask  = (const int*)d_in[1];
    const float* w_qkv  = (const float*)d_in[2];
    const float* w_proj = (const float*)d_in[3];
    float* out = (float*)d_out;

    k_qkv<<<dim3(48, 32), 256>>>(x, w_qkv);
    k_rope<<<(B_ * H_ * L_ * 64) / 256, 256>>>();
    k_scores<<<dim3(16, 16, 32), 256>>>(amask);
    k_softmax<<<B_ * H_ * L_, 256>>>();
    k_pv<<<dim3(1, 16, 32), 256>>>();
    k_proj<<<dim3(16, 32), 256>>>(w_proj, out);
}

// round 2
// speedup vs baseline: 2.4752x; 2.4752x over previous
#include <cuda_runtime.h>
#include <math.h>
#include <stdint.h>

#define B_  2
#define L_  2048
#define D_  2048
#define H_  16
#define DH  128
#define BH  (B_*H_)
#define NEGV  (-1000000000.0f)
#define SCALE 0.08838834764831845f
#define SMPAD 36

// ---------------- scratch (device globals; no runtime allocation) ----------
__device__ float g_Q[B_*H_*L_*DH];            // [B,H,L,Dh]
__device__ float g_K[B_*H_*L_*DH];            // [B,H,L,Dh]
__device__ float g_V[B_*H_*DH*L_];            // [B,H,Dh,L]  (transposed!)
__device__ float g_S[(size_t)B_*H_*L_*L_];    // [B*H, L, L]
__device__ float g_Y[B_*L_*D_];               // [B,L,D]
__device__ float g_WT1[3*D_*D_];              // w_qkv^T  [6144,2048]
__device__ float g_WT2[D_*D_];                // w_proj^T [2048,2048]

// ---------------------------- helpers -------------------------------------
__device__ __forceinline__ float tf32r(float x) {
    uint32_t u; asm("cvt.rna.tf32.f32 %0, %1;" : "=r"(u) : "f"(x));
    return __uint_as_float(u);
}

__device__ __forceinline__ void mma_tf32(float* c, const uint32_t* a, const uint32_t* b) {
    asm volatile(
        "mma.sync.aligned.m16n8k8.row.col.f32.tf32.tf32.f32 "
        "{%0,%1,%2,%3},{%4,%5,%6,%7},{%8,%9},{%0,%1,%2,%3};\n"
        : "+f"(c[0]), "+f"(c[1]), "+f"(c[2]), "+f"(c[3])
        : "r"(a[0]), "r"(a[1]), "r"(a[2]), "r"(a[3]), "r"(b[0]), "r"(b[1]));
}

// 128x128 block tile, K-step 32, 256 threads = 8 warps (2m x 4n), 64x32/warp.
// A: [128 rows, K] K-major (lda). B: [128 "n" rows, K] K-major (ldb).
__device__ __forceinline__ void gemm_tf32(
    const float* __restrict__ Ab, int lda,
    const float* __restrict__ Bb, int ldb,
    int kTiles, float (&acc)[4][4][4])
{
    __shared__ float As[128][SMPAD];
    __shared__ float Bs[128][SMPAD];
    const int tid  = threadIdx.x;
    const int lane = tid & 31, warp = tid >> 5;
    const int wm = warp >> 2, wn = warp & 3;
    const int lr = tid >> 1, lc = (tid & 1) * 16;
    const int r = lane >> 2, c = lane & 3;
    const float* Ag = Ab + (size_t)lr * lda + lc;
    const float* Bg = Bb + (size_t)lr * ldb + lc;

    float4 avr[4], bvr[4];
#pragma unroll
    for (int i = 0; i < 4; i++) {
        avr[i] = *(const float4*)(Ag + i * 4);
        bvr[i] = *(const float4*)(Bg + i * 4);
    }
    for (int kt = 0; kt < kTiles; kt++) {
        __syncthreads();
#pragma unroll
        for (int i = 0; i < 4; i++) {
            As[lr][lc + i*4 + 0] = tf32r(avr[i].x);
            As[lr][lc + i*4 + 1] = tf32r(avr[i].y);
            As[lr][lc + i*4 + 2] = tf32r(avr[i].z);
            As[lr][lc + i*4 + 3] = tf32r(avr[i].w);
            Bs[lr][lc + i*4 + 0] = tf32r(bvr[i].x);
            Bs[lr][lc + i*4 + 1] = tf32r(bvr[i].y);
            Bs[lr][lc + i*4 + 2] = tf32r(bvr[i].z);
            Bs[lr][lc + i*4 + 3] = tf32r(bvr[i].w);
        }
        __syncthreads();
        if (kt + 1 < kTiles) {   // prefetch next tile while computing this one
            const float* Ag2 = Ag + (kt + 1) * 32;
            const float* Bg2 = Bb == nullptr ? nullptr : Bg + (kt + 1) * 32;
#pragma unroll
            for (int i = 0; i < 4; i++) {
                avr[i] = *(const float4*)(Ag2 + i * 4);
                bvr[i] = *(const float4*)(Bg2 + i * 4);
            }
        }
#pragma unroll
        for (int k0 = 0; k0 < 32; k0 += 8) {
            uint32_t af[4][4], bf[4][2];
#pragma unroll
            for (int mi = 0; mi < 4; mi++) {
                int row = wm * 64 + mi * 16 + r;
                af[mi][0] = __float_as_uint(As[row][k0 + c]);
                af[mi][1] = __float_as_uint(As[row + 8][k0 + c]);
                af[mi][2] = __float_as_uint(As[row][k0 + c + 4]);
                af[mi][3] = __float_as_uint(As[row + 8][k0 + c + 4]);
            }
#pragma unroll
            for (int ni = 0; ni < 4; ni++) {
                int col = wn * 32 + ni * 8 + r;
                bf[ni][0] = __float_as_uint(Bs[col][k0 + c]);
                bf[ni][1] = __float_as_uint(Bs[col][k0 + c + 4]);
            }
#pragma unroll
            for (int mi = 0; mi < 4; mi++)
#pragma unroll
                for (int ni = 0; ni < 4; ni++)
                    mma_tf32(acc[mi][ni], af[mi], bf[ni]);
        }
    }
}

#define ACC_ZERO(acc)                                   \
    _Pragma("unroll") for (int _i = 0; _i < 4; _i++)    \
    _Pragma("unroll") for (int _j = 0; _j < 4; _j++)    \
    _Pragma("unroll") for (int _k = 0; _k < 4; _k++) acc[_i][_j][_k] = 0.f;

// -------------------------- weight transpose -------------------------------
__global__ __launch_bounds__(256) void k_transpose(const float* __restrict__ src,
                                                   float* __restrict__ dst,
                                                   int R, int C) {
    __shared__ float t[32][33];
    int bx = blockIdx.x * 32, by = blockIdx.y * 32;
    int x = bx + threadIdx.x;
#pragma unroll
    for (int i = 0; i < 32; i += 8)
        t[threadIdx.y + i][threadIdx.x] = src[(size_t)(by + threadIdx.y + i) * C + x];
    __syncthreads();
    int x2 = by + threadIdx.x;
#pragma unroll
    for (int i = 0; i < 32; i += 8)
        dst[(size_t)(bx + threadIdx.y + i) * R + x2] = t[threadIdx.x][threadIdx.y + i];
}

// ============ GEMM 1: qkv = x @ w_qkv -> scatter Q/K/V(+transpose V) =======
__global__ __launch_bounds__(256) void k_qkv(const float* __restrict__ x) {
    const int bn = blockIdx.x, bm = blockIdx.y;
    float acc[4][4][4];
    ACC_ZERO(acc);
    gemm_tf32(x + (size_t)bm * 128 * D_, D_,
              g_WT1 + (size_t)bn * 128 * D_, D_, D_ / 32, acc);

    const int lane = threadIdx.x & 31, warp = threadIdx.x >> 5;
    const int wm = warp >> 2, wn = warp & 3;
#pragma unroll
    for (int mi = 0; mi < 4; mi++)
#pragma unroll
        for (int ni = 0; ni < 4; ni++)
#pragma unroll
            for (int rg = 0; rg < 4; rg++) {
                int row = wm * 64 + mi * 16 + (lane >> 2) + ((rg >> 1) ? 8 : 0);
                int col = wn * 32 + ni * 8 + 2 * (lane & 3) + (rg & 1);
                int m = bm * 128 + row, n = bn * 128 + col;
                int bb = m >> 11, l = m & 2047;
                int part = n >> 11, idx = n & 2047;
                int h = idx >> 7, d = idx & 127;
                float v = acc[mi][ni][rg];
                if (part == 2)
                    g_V[(((size_t)bb * H_ + h) * DH + d) * L_ + l] = v;
                else if (part == 1)
                    g_K[(((size_t)bb * H_ + h) * L_ + l) * DH + d] = v;
                else
                    g_Q[(((size_t)bb * H_ + h) * L_ + l) * DH + d] = v;
            }
}

// ======================= RoPE on Q and K, in place ========================
__global__ void k_rope() {
    int idx = blockIdx.x * blockDim.x + threadIdx.x;
    int i   = idx & 63;
    int bhl = idx >> 6;
    int l   = bhl & 2047;
    float inv_freq = powf(10000.0f, -(float)(2 * i) * (1.0f / 128.0f));
    float ang = (float)l * inv_freq;
    float s, cc;
    sincosf(ang, &s, &cc);
    int base = bhl << 7;
    float q0 = g_Q[base + i], q1 = g_Q[base + i + 64];
    g_Q[base + i]      = q0 * cc - q1 * s;
    g_Q[base + i + 64] = q1 * cc + q0 * s;
    float k0 = g_K[base + i], k1 = g_K[base + i + 64];
    g_K[base + i]      = k0 * cc - k1 * s;
    g_K[base + i + 64] = k1 * cc + k0 * s;
}

// ============= GEMM 2: S = Q @ K^T * scale, causal + pad mask =============
__global__ __launch_bounds__(256) void k_scores(const int* __restrict__ amask) {
    const int bn = blockIdx.x, bm = blockIdx.y, bh = blockIdx.z;
    const int bb = bh >> 4;
    float acc[4][4][4];
    ACC_ZERO(acc);
    if (bn <= bm)
        gemm_tf32(g_Q + (size_t)bh * L_ * DH + (size_t)bm * 128 * DH, DH,
                  g_K + (size_t)bh * L_ * DH + (size_t)bn * 128 * DH, DH,
                  DH / 32, acc);

    const int lane = threadIdx.x & 31, warp = threadIdx.x >> 5;
    const int wm = warp >> 2, wn = warp & 3;
    float* Sp = g_S + (size_t)bh * L_ * L_;
#pragma unroll
    for (int mi = 0; mi < 4; mi++)
#pragma unroll
        for (int ni = 0; ni < 4; ni++)
#pragma unroll
            for (int rg = 0; rg < 4; rg++) {
                int row = wm * 64 + mi * 16 + (lane >> 2) + ((rg >> 1) ? 8 : 0);
                int col = wn * 32 + ni * 8 + 2 * (lane & 3) + (rg & 1);
                int q = bm * 128 + row, kc = bn * 128 + col;
                bool valid = (kc <= q) && (amask[bb * L_ + kc] != 0);
                Sp[(size_t)q * L_ + kc] = valid ? acc[mi][ni][rg] * SCALE : NEGV;
            }
}

// ============================ row softmax =================================
__global__ __launch_bounds__(256) void k_softmax() {
    __shared__ float red[256];
    float* row = g_S + (size_t)blockIdx.x * L_;
    int t = threadIdx.x;
    float v[8];
    float mx = -3.4e38f;
#pragma unroll
    for (int i = 0; i < 8; i++) { v[i] = row[t + 256 * i]; mx = fmaxf(mx, v[i]); }
    red[t] = mx; __syncthreads();
    for (int s = 128; s > 0; s >>= 1) {
        if (t < s) red[t] = fmaxf(red[t], red[t + s]);
        __syncthreads();
    }
    mx = red[0];
    __syncthreads();
    float sum = 0.f;
#pragma unroll
    for (int i = 0; i < 8; i++) { v[i] = expf(v[i] - mx); sum += v[i]; }
    red[t] = sum; __syncthreads();
    for (int s = 128; s > 0; s >>= 1) {
        if (t < s) red[t] += red[t + s];
        __syncthreads();
    }
    float inv = 1.0f / red[0];
#pragma unroll
    for (int i = 0; i < 8; i++) row[t + 256 * i] = v[i] * inv;
}

// ============== GEMM 3: Y = P @ V, scatter to [B,L,D] =====================
__global__ __launch_bounds__(256) void k_pv() {
    const int bm = blockIdx.y, bh = blockIdx.z;
    float acc[4][4][4];
    ACC_ZERO(acc);
    gemm_tf32(g_S + (size_t)bh * L_ * L_ + (size_t)bm * 128 * L_, L_,
              g_V + (size_t)bh * DH * L_, L_,
              (bm + 1) * 4, acc);   // causal: P == 0 beyond (bm+1)*128

    const int lane = threadIdx.x & 31, warp = threadIdx.x >> 5;
    const int wm = warp >> 2, wn = warp & 3;
    const int bb = bh >> 4, h = bh & 15;
#pragma unroll
    for (int mi = 0; mi < 4; mi++)
#pragma unroll
        for (int ni = 0; ni < 4; ni++)
#pragma unroll
            for (int rg = 0; rg < 4; rg++) {
                int row = wm * 64 + mi * 16 + (lane >> 2) + ((rg >> 1) ? 8 : 0);
                int col = wn * 32 + ni * 8 + 2 * (lane & 3) + (rg & 1);
                int l = bm * 128 + row;
                g_Y[((size_t)bb * L_ + l) * D_ + h * DH + col] = acc[mi][ni][rg];
            }
}

// ================= GEMM 4: out = Y @ w_proj ===============================
__global__ __launch_bounds__(256) void k_proj(float* __restrict__ out) {
    const int bn = blockIdx.x, bm = blockIdx.y;
    float acc[4][4][4];
    ACC_ZERO(acc);
    gemm_tf32(g_Y + (size_t)bm * 128 * D_, D_,
              g_WT2 + (size_t)bn * 128 * D_, D_, D_ / 32, acc);

    const int lane = threadIdx.x & 31, warp = threadIdx.x >> 5;
    const int wm = warp >> 2, wn = warp & 3;
#pragma unroll
    for (int mi = 0; mi < 4; mi++)
#pragma unroll
        for (int ni = 0; ni < 4; ni++)
#pragma unroll
            for (int rg = 0; rg < 4; rg++) {
                int row = wm * 64 + mi * 16 + (lane >> 2) + ((rg >> 1) ? 8 : 0);
                int col = wn * 32 + ni * 8 + 2 * (lane & 3) + (rg & 1);
                int m = bm * 128 + row, n = bn * 128 + col;
                out[(size_t)m * D_ + n] = acc[mi][ni][rg];
            }
}

// ============================== launcher ==================================
extern "C" void kernel_launch(void* const* d_in, const int* in_sizes, int n_in,
                              void* d_out, int out_size) {
    const float* x      = (const float*)d_in[0];
    const int*   amask  = (const int*)d_in[1];
    const float* w_qkv  = (const float*)d_in[2];
    const float* w_proj = (const float*)d_in[3];
    float* out = (float*)d_out;

    float* wt1; cudaGetSymbolAddress((void**)&wt1, g_WT1);
    float* wt2; cudaGetSymbolAddress((void**)&wt2, g_WT2);

    k_transpose<<<dim3(3 * D_ / 32, D_ / 32), dim3(32, 8)>>>(w_qkv, wt1, D_, 3 * D_);
    k_transpose<<<dim3(D_ / 32, D_ / 32), dim3(32, 8)>>>(w_proj, wt2, D_, D_);
    k_qkv<<<dim3(48, 32), 256>>>(x);
    k_rope<<<(B_ * H_ * L_ * 64) / 256, 256>>>();
    k_scores<<<dim3(16, 16, 32), 256>>>(amask);
    k_softmax<<<B_ * H_ * L_, 256>>>();
    k_pv<<<dim3(1, 16, 32), 256>>>();
    k_proj<<<dim3(16, 32), 256>>>(out);
}

// round 3
// speedup vs baseline: 2.9087x; 1.1751x over previous
#include <cuda_runtime.h>
#include <math.h>
#include <stdint.h>

#define B_  2
#define L_  2048
#define D_  2048
#define H_  16
#define DH  128
#define BH  (B_*H_)
#define NEGV  (-1000000000.0f)
#define SCALE 0.08838834764831845f
#define SMPAD 36
#define SMS   132            // fused-kernel smem row stride (floats)

// ---------------- scratch (device globals; no runtime allocation) ----------
__device__ float g_Q[B_*H_*L_*DH];            // [B,H,L,Dh]
__device__ float g_K[B_*H_*L_*DH];            // [B,H,L,Dh]
__device__ float g_V[B_*H_*DH*L_];            // [B,H,Dh,L]  (transposed!)
__device__ float g_Y[B_*L_*D_];               // [B,L,D]
__device__ float g_WT1[3*D_*D_];              // w_qkv^T  [6144,2048]
__device__ float g_WT2[D_*D_];                // w_proj^T [2048,2048]

// ---------------------------- helpers -------------------------------------
__device__ __forceinline__ float tf32r(float x) {
    uint32_t u; asm("cvt.rna.tf32.f32 %0, %1;" : "=r"(u) : "f"(x));
    return __uint_as_float(u);
}

__device__ __forceinline__ void mma_tf32(float* c, const uint32_t* a, const uint32_t* b) {
    asm volatile(
        "mma.sync.aligned.m16n8k8.row.col.f32.tf32.tf32.f32 "
        "{%0,%1,%2,%3},{%4,%5,%6,%7},{%8,%9},{%0,%1,%2,%3};\n"
        : "+f"(c[0]), "+f"(c[1]), "+f"(c[2]), "+f"(c[3])
        : "r"(a[0]), "r"(a[1]), "r"(a[2]), "r"(a[3]), "r"(b[0]), "r"(b[1]));
}

// 128x128 block tile, K-step 32, 256 threads = 8 warps (2m x 4n), 64x32/warp.
__device__ __forceinline__ void gemm_tf32(
    const float* __restrict__ Ab, int lda,
    const float* __restrict__ Bb, int ldb,
    int kTiles, float (&acc)[4][4][4])
{
    __shared__ float As[128][SMPAD];
    __shared__ float Bs[128][SMPAD];
    const int tid  = threadIdx.x;
    const int lane = tid & 31, warp = tid >> 5;
    const int wm = warp >> 2, wn = warp & 3;
    const int lr = tid >> 1, lc = (tid & 1) * 16;
    const int r = lane >> 2, c = lane & 3;
    const float* Ag = Ab + (size_t)lr * lda + lc;
    const float* Bg = Bb + (size_t)lr * ldb + lc;

    float4 avr[4], bvr[4];
#pragma unroll
    for (int i = 0; i < 4; i++) {
        avr[i] = *(const float4*)(Ag + i * 4);
        bvr[i] = *(const float4*)(Bg + i * 4);
    }
    for (int kt = 0; kt < kTiles; kt++) {
        __syncthreads();
#pragma unroll
        for (int i = 0; i < 4; i++) {
            As[lr][lc + i*4 + 0] = tf32r(avr[i].x);
            As[lr][lc + i*4 + 1] = tf32r(avr[i].y);
            As[lr][lc + i*4 + 2] = tf32r(avr[i].z);
            As[lr][lc + i*4 + 3] = tf32r(avr[i].w);
            Bs[lr][lc + i*4 + 0] = tf32r(bvr[i].x);
            Bs[lr][lc + i*4 + 1] = tf32r(bvr[i].y);
            Bs[lr][lc + i*4 + 2] = tf32r(bvr[i].z);
            Bs[lr][lc + i*4 + 3] = tf32r(bvr[i].w);
        }
        __syncthreads();
        if (kt + 1 < kTiles) {
            const float* Ag2 = Ag + (kt + 1) * 32;
            const float* Bg2 = Bg + (kt + 1) * 32;
#pragma unroll
            for (int i = 0; i < 4; i++) {
                avr[i] = *(const float4*)(Ag2 + i * 4);
                bvr[i] = *(const float4*)(Bg2 + i * 4);
            }
        }
#pragma unroll
        for (int k0 = 0; k0 < 32; k0 += 8) {
            uint32_t af[4][4], bf[4][2];
#pragma unroll
            for (int mi = 0; mi < 4; mi++) {
                int row = wm * 64 + mi * 16 + r;
                af[mi][0] = __float_as_uint(As[row][k0 + c]);
                af[mi][1] = __float_as_uint(As[row + 8][k0 + c]);
                af[mi][2] = __float_as_uint(As[row][k0 + c + 4]);
                af[mi][3] = __float_as_uint(As[row + 8][k0 + c + 4]);
            }
#pragma unroll
            for (int ni = 0; ni < 4; ni++) {
                int col = wn * 32 + ni * 8 + r;
                bf[ni][0] = __float_as_uint(Bs[col][k0 + c]);
                bf[ni][1] = __float_as_uint(Bs[col][k0 + c + 4]);
            }
#pragma unroll
            for (int mi = 0; mi < 4; mi++)
#pragma unroll
                for (int ni = 0; ni < 4; ni++)
                    mma_tf32(acc[mi][ni], af[mi], bf[ni]);
        }
    }
}

#define ACC_ZERO(acc)                                   \
    _Pragma("unroll") for (int _i = 0; _i < 4; _i++)    \
    _Pragma("unroll") for (int _j = 0; _j < 4; _j++)    \
    _Pragma("unroll") for (int _k = 0; _k < 4; _k++) acc[_i][_j][_k] = 0.f;

// -------------------------- weight transpose -------------------------------
__global__ __launch_bounds__(256) void k_transpose(const float* __restrict__ src,
                                                   float* __restrict__ dst,
                                                   int R, int C) {
    __shared__ float t[32][33];
    int bx = blockIdx.x * 32, by = blockIdx.y * 32;
    int x = bx + threadIdx.x;
#pragma unroll
    for (int i = 0; i < 32; i += 8)
        t[threadIdx.y + i][threadIdx.x] = src[(size_t)(by + threadIdx.y + i) * C + x];
    __syncthreads();
    int x2 = by + threadIdx.x;
#pragma unroll
    for (int i = 0; i < 32; i += 8)
        dst[(size_t)(bx + threadIdx.y + i) * R + x2] = t[threadIdx.x][threadIdx.y + i];
}

// ============ GEMM 1: qkv = x @ w_qkv -> scatter Q/K/V(+transpose V) =======
__global__ __launch_bounds__(256) void k_qkv(const float* __restrict__ x) {
    const int bn = blockIdx.x, bm = blockIdx.y;
    float acc[4][4][4];
    ACC_ZERO(acc);
    gemm_tf32(x + (size_t)bm * 128 * D_, D_,
              g_WT1 + (size_t)bn * 128 * D_, D_, D_ / 32, acc);

    const int lane = threadIdx.x & 31, warp = threadIdx.x >> 5;
    const int wm = warp >> 2, wn = warp & 3;
#pragma unroll
    for (int mi = 0; mi < 4; mi++)
#pragma unroll
        for (int ni = 0; ni < 4; ni++)
#pragma unroll
            for (int rg = 0; rg < 4; rg++) {
                int row = wm * 64 + mi * 16 + (lane >> 2) + ((rg >> 1) ? 8 : 0);
                int col = wn * 32 + ni * 8 + 2 * (lane & 3) + (rg & 1);
                int m = bm * 128 + row, n = bn * 128 + col;
                int bb = m >> 11, l = m & 2047;
                int part = n >> 11, idx = n & 2047;
                int h = idx >> 7, d = idx & 127;
                float v = acc[mi][ni][rg];
                if (part == 2)
                    g_V[(((size_t)bb * H_ + h) * DH + d) * L_ + l] = v;
                else if (part == 1)
                    g_K[(((size_t)bb * H_ + h) * L_ + l) * DH + d] = v;
                else
                    g_Q[(((size_t)bb * H_ + h) * L_ + l) * DH + d] = v;
            }
}

// ======================= RoPE on Q and K, in place ========================
__global__ void k_rope() {
    int idx = blockIdx.x * blockDim.x + threadIdx.x;
    int i   = idx & 63;
    int bhl = idx >> 6;
    int l   = bhl & 2047;
    float inv_freq = powf(10000.0f, -(float)(2 * i) * (1.0f / 128.0f));
    float ang = (float)l * inv_freq;
    float s, cc;
    sincosf(ang, &s, &cc);
    int base = bhl << 7;
    float q0 = g_Q[base + i], q1 = g_Q[base + i + 64];
    g_Q[base + i]      = q0 * cc - q1 * s;
    g_Q[base + i + 64] = q1 * cc + q0 * s;
    float k0 = g_K[base + i], k1 = g_K[base + i + 64];
    g_K[base + i]      = k0 * cc - k1 * s;
    g_K[base + i + 64] = k1 * cc + k0 * s;
}

// ======== fused flash attention: per (bh, 128-q-block) CTA ================
// dyn smem: Qs[128][SMS] | Ks/Ps[128][SMS] | Vs[128][SMS] | red1[128][4] |
//           red2[128][4] | am_s[128]
#define SM_Q   0
#define SM_K   (128*SMS)
#define SM_V   (2*128*SMS)
#define SM_R1  (3*128*SMS)
#define SM_R2  (SM_R1 + 512)
#define SM_AM  (SM_R2 + 512)
#define SM_TOT ((SM_AM + 128) * 4)

__global__ __launch_bounds__(256, 1) void k_attn(const int* __restrict__ amask) {
    extern __shared__ float sm[];
    float* Qs = sm + SM_Q;
    float* Ks = sm + SM_K;      // reused as Ps
    float* Vs = sm + SM_V;
    float* red1 = sm + SM_R1;
    float* red2 = sm + SM_R2;
    int*   am_s = (int*)(sm + SM_AM);

    const int bm = 15 - blockIdx.x;           // largest q-block first
    const int bh = blockIdx.y;
    const int bb = bh >> 4, hh = bh & 15;
    const int tid = threadIdx.x;
    const int lane = tid & 31, warp = tid >> 5;
    const int wm = warp >> 2, wn = warp & 3;
    const int r = lane >> 2, c = lane & 3;

    // --- load Q block (pre-scaled, tf32) ---
    const float* Qg = g_Q + (size_t)bh * L_ * DH + (size_t)bm * 128 * DH;
#pragma unroll
    for (int i = 0; i < 16; i++) {
        int idx = i * 256 + tid;
        int row = idx >> 5, cg = (idx & 31) * 4;
        float4 v = *(const float4*)(Qg + (size_t)row * DH + cg);
        Qs[row * SMS + cg + 0] = tf32r(v.x * SCALE);
        Qs[row * SMS + cg + 1] = tf32r(v.y * SCALE);
        Qs[row * SMS + cg + 2] = tf32r(v.z * SCALE);
        Qs[row * SMS + cg + 3] = tf32r(v.w * SCALE);
    }

    float oacc[4][4][4];
    ACC_ZERO(oacc);
    float mrow[4][2], lrow[4][2];
#pragma unroll
    for (int mi = 0; mi < 4; mi++)
#pragma unroll
        for (int h = 0; h < 2; h++) { mrow[mi][h] = -3.0e38f; lrow[mi][h] = 0.f; }

    for (int kb = 0; kb <= bm; kb++) {
        __syncthreads();   // prev iter's PV done (Ks/Vs free); Q stores done
        // --- load K, V tiles (tf32) + amask column chunk ---
        const float* Kg = g_K + (size_t)bh * L_ * DH + (size_t)kb * 128 * DH;
        const float* Vg = g_V + (size_t)bh * DH * L_ + (size_t)kb * 128;
#pragma unroll
        for (int i = 0; i < 16; i++) {
            int idx = i * 256 + tid;
            int row = idx >> 5, cg = (idx & 31) * 4;
            float4 kv = *(const float4*)(Kg + (size_t)row * DH + cg);
            Ks[row * SMS + cg + 0] = tf32r(kv.x);
            Ks[row * SMS + cg + 1] = tf32r(kv.y);
            Ks[row * SMS + cg + 2] = tf32r(kv.z);
            Ks[row * SMS + cg + 3] = tf32r(kv.w);
            float4 vv = *(const float4*)(Vg + (size_t)row * L_ + cg);
            Vs[row * SMS + cg + 0] = tf32r(vv.x);
            Vs[row * SMS + cg + 1] = tf32r(vv.y);
            Vs[row * SMS + cg + 2] = tf32r(vv.z);
            Vs[row * SMS + cg + 3] = tf32r(vv.w);
        }
        if (tid < 128) am_s[tid] = amask[bb * L_ + kb * 128 + tid];
        __syncthreads();

        // --- S = Qs @ Ks^T (already scaled) ---
        float sacc[4][4][4];
        ACC_ZERO(sacc);
#pragma unroll
        for (int k0 = 0; k0 < 128; k0 += 8) {
            uint32_t af[4][4], bf[4][2];
#pragma unroll
            for (int mi = 0; mi < 4; mi++) {
                int row = wm * 64 + mi * 16 + r;
                af[mi][0] = __float_as_uint(Qs[row * SMS + k0 + c]);
                af[mi][1] = __float_as_uint(Qs[(row + 8) * SMS + k0 + c]);
                af[mi][2] = __float_as_uint(Qs[row * SMS + k0 + c + 4]);
                af[mi][3] = __float_as_uint(Qs[(row + 8) * SMS + k0 + c + 4]);
            }
#pragma unroll
            for (int ni = 0; ni < 4; ni++) {
                int col = wn * 32 + ni * 8 + r;
                bf[ni][0] = __float_as_uint(Ks[col * SMS + k0 + c]);
                bf[ni][1] = __float_as_uint(Ks[col * SMS + k0 + c + 4]);
            }
#pragma unroll
            for (int mi = 0; mi < 4; mi++)
#pragma unroll
                for (int ni = 0; ni < 4; ni++)
                    mma_tf32(sacc[mi][ni], af[mi], bf[ni]);
        }

        // --- mask ---
        int amf[4][2];
#pragma unroll
        for (int ni = 0; ni < 4; ni++)
#pragma unroll
            for (int par = 0; par < 2; par++)
                amf[ni][par] = am_s[wn * 32 + ni * 8 + 2 * c + par];
        const bool diag = (kb == bm);
#pragma unroll
        for (int mi = 0; mi < 4; mi++)
#pragma unroll
            for (int ni = 0; ni < 4; ni++)
#pragma unroll
                for (int rg = 0; rg < 4; rg++) {
                    bool ok = amf[ni][rg & 1] != 0;
                    if (diag) {
                        int qr = bm * 128 + wm * 64 + mi * 16 + r + ((rg >> 1) ? 8 : 0);
                        int kc = kb * 128 + wn * 32 + ni * 8 + 2 * c + (rg & 1);
                        ok = ok && (kc <= qr);
                    }
                    if (!ok) sacc[mi][ni][rg] = NEGV;
                }

        // --- rowmax (warp quad -> smem across 4 n-warps) ---
#pragma unroll
        for (int mi = 0; mi < 4; mi++)
#pragma unroll
            for (int h = 0; h < 2; h++) {
                float pm = -3.0e38f;
#pragma unroll
                for (int ni = 0; ni < 4; ni++)
                    pm = fmaxf(pm, fmaxf(sacc[mi][ni][2 * h], sacc[mi][ni][2 * h + 1]));
                pm = fmaxf(pm, __shfl_xor_sync(0xffffffff, pm, 1));
                pm = fmaxf(pm, __shfl_xor_sync(0xffffffff, pm, 2));
                if (c == 0)
                    red1[(wm * 64 + mi * 16 + r + 8 * h) * 4 + wn] = pm;
            }
        __syncthreads();   // red1 ready; also: all warps done reading Ks

        float mnew[4][2], sfac[4][2];
#pragma unroll
        for (int mi = 0; mi < 4; mi++)
#pragma unroll
            for (int h = 0; h < 2; h++) {
                int row = wm * 64 + mi * 16 + r + 8 * h;
                float mb = fmaxf(fmaxf(red1[row * 4 + 0], red1[row * 4 + 1]),
                                 fmaxf(red1[row * 4 + 2], red1[row * 4 + 3]));
                float mn = fmaxf(mrow[mi][h], mb);
                sfac[mi][h] = __expf(mrow[mi][h] - mn);
                mnew[mi][h] = mn;
                mrow[mi][h] = mn;
            }

        // --- exp, partial row sums, rescale O, store P (into Ks buffer) ---
#pragma unroll
        for (int mi = 0; mi < 4; mi++)
#pragma unroll
            for (int h = 0; h < 2; h++) {
                float ps = 0.f;
#pragma unroll
                for (int ni = 0; ni < 4; ni++) {
                    float p0 = __expf(sacc[mi][ni][2 * h]     - mnew[mi][h]);
                    float p1 = __expf(sacc[mi][ni][2 * h + 1] - mnew[mi][h]);
                    sacc[mi][ni][2 * h]     = p0;
                    sacc[mi][ni][2 * h + 1] = p1;
                    ps += p0 + p1;
                    oacc[mi][ni][2 * h]     *= sfac[mi][h];
                    oacc[mi][ni][2 * h + 1] *= sfac[mi][h];
                }
                ps += __shfl_xor_sync(0xffffffff, ps, 1);
                ps += __shfl_xor_sync(0xffffffff, ps, 2);
                int row = wm * 64 + mi * 16 + r + 8 * h;
                if (c == 0) red2[row * 4 + wn] = ps;
                lrow[mi][h] *= sfac[mi][h];
                // store P (tf32) into Ks buffer (safe: Ks dead after sync above)
#pragma unroll
                for (int ni = 0; ni < 4; ni++) {
                    float2 p2;
                    p2.x = tf32r(sacc[mi][ni][2 * h]);
                    p2.y = tf32r(sacc[mi][ni][2 * h + 1]);
                    *(float2*)&Ks[row * SMS + wn * 32 + ni * 8 + 2 * c] = p2;
                }
            }
        __syncthreads();   // P + red2 visible everywhere

#pragma unroll
        for (int mi = 0; mi < 4; mi++)
#pragma unroll
            for (int h = 0; h < 2; h++) {
                int row = wm * 64 + mi * 16 + r + 8 * h;
                lrow[mi][h] += red2[row * 4 + 0] + red2[row * 4 + 1] +
                               red2[row * 4 + 2] + red2[row * 4 + 3];
            }

        // --- O += P @ V  (A from Ps=Ks buffer, B from Vs[d][l]) ---
#pragma unroll
        for (int k0 = 0; k0 < 128; k0 += 8) {
            uint32_t af[4][4], bf[4][2];
#pragma unroll
            for (int mi = 0; mi < 4; mi++) {
                int row = wm * 64 + mi * 16 + r;
                af[mi][0] = __float_as_uint(Ks[row * SMS + k0 + c]);
                af[mi][1] = __float_as_uint(Ks[(row + 8) * SMS + k0 + c]);
                af[mi][2] = __float_as_uint(Ks[row * SMS + k0 + c + 4]);
                af[mi][3] = __float_as_uint(Ks[(row + 8) * SMS + k0 + c + 4]);
            }
#pragma unroll
            for (int ni = 0; ni < 4; ni++) {
                int col = wn * 32 + ni * 8 + r;
                bf[ni][0] = __float_as_uint(Vs[col * SMS + k0 + c]);
                bf[ni][1] = __float_as_uint(Vs[col * SMS + k0 + c + 4]);
            }
#pragma unroll
            for (int mi = 0; mi < 4; mi++)
#pragma unroll
                for (int ni = 0; ni < 4; ni++)
                    mma_tf32(oacc[mi][ni], af[mi], bf[ni]);
        }
    }

    // --- epilogue: O /= l, write to g_Y[bb, q, hh*128 + d] ---
#pragma unroll
    for (int mi = 0; mi < 4; mi++)
#pragma unroll
        for (int h = 0; h < 2; h++) {
            float inv = 1.0f / lrow[mi][h];
            int qg = bm * 128 + wm * 64 + mi * 16 + r + 8 * h;
#pragma unroll
            for (int ni = 0; ni < 4; ni++) {
                float2 o2;
                o2.x = oacc[mi][ni][2 * h]     * inv;
                o2.y = oacc[mi][ni][2 * h + 1] * inv;
                int col = hh * DH + wn * 32 + ni * 8 + 2 * c;
                *(float2*)&g_Y[(size_t)(bb * L_ + qg) * D_ + col] = o2;
            }
        }
}

// ================= GEMM 4: out = Y @ w_proj ===============================
__global__ __launch_bounds__(256) void k_proj(float* __restrict__ out) {
    const int bn = blockIdx.x, bm = blockIdx.y;
    float acc[4][4][4];
    ACC_ZERO(acc);
    gemm_tf32(g_Y + (size_t)bm * 128 * D_, D_,
              g_WT2 + (size_t)bn * 128 * D_, D_, D_ / 32, acc);

    const int lane = threadIdx.x & 31, warp = threadIdx.x >> 5;
    const int wm = warp >> 2, wn = warp & 3;
#pragma unroll
    for (int mi = 0; mi < 4; mi++)
#pragma unroll
        for (int ni = 0; ni < 4; ni++)
#pragma unroll
            for (int rg = 0; rg < 4; rg++) {
                int row = wm * 64 + mi * 16 + (lane >> 2) + ((rg >> 1) ? 8 : 0);
                int col = wn * 32 + ni * 8 + 2 * (lane & 3) + (rg & 1);
                int m = bm * 128 + row, n = bn * 128 + col;
                out[(size_t)m * D_ + n] = acc[mi][ni][rg];
            }
}

// ============================== launcher ==================================
extern "C" void kernel_launch(void* const* d_in, const int* in_sizes, int n_in,
                              void* d_out, int out_size) {
    const float* x      = (const float*)d_in[0];
    const int*   amask  = (const int*)d_in[1];
    const float* w_qkv  = (const float*)d_in[2];
    const float* w_proj = (const float*)d_in[3];
    float* out = (float*)d_out;

    float* wt1; cudaGetSymbolAddress((void**)&wt1, g_WT1);
    float* wt2; cudaGetSymbolAddress((void**)&wt2, g_WT2);

    static bool attr_done = false;
    if (!attr_done) {
        cudaFuncSetAttribute(k_attn, cudaFuncAttributeMaxDynamicSharedMemorySize,
                             SM_TOT);
        attr_done = true;
    }

    k_transpose<<<dim3(3 * D_ / 32, D_ / 32), dim3(32, 8)>>>(w_qkv, wt1, D_, 3 * D_);
    k_transpose<<<dim3(D_ / 32, D_ / 32), dim3(32, 8)>>>(w_proj, wt2, D_, D_);
    k_qkv<<<dim3(48, 32), 256>>>(x);
    k_rope<<<(B_ * H_ * L_ * 64) / 256, 256>>>();
    k_attn<<<dim3(16, 32), 256, SM_TOT>>>(amask);
    k_proj<<<dim3(16, 32), 256>>>(out);
}

// round 4
// speedup vs baseline: 3.5857x; 1.2328x over previous
#include <cuda_runtime.h>
#include <math.h>
#include <stdint.h>

#define B_  2
#define L_  2048
#define D_  2048
#define H_  16
#define DH  128
#define NEGV  (-1000000000.0f)
#define SCALE 0.08838834764831845f
#define SMS   132            // attn smem row stride (floats)
#define GS    36             // gemm smem row stride (floats)
#define STAGE_F (384*GS)     // floats per stage (A 128 rows + B 256 rows)
#define BOFF_F  (128*GS)
#define GEMM_SMEM (2*STAGE_F*4)

// ---------------- scratch (device globals; no runtime allocation) ----------
__device__ float g_X[B_*L_*D_];               // tf32(x)
__device__ float g_Q[B_*H_*L_*DH];            // [B,H,L,Dh]  tf32 after rope
__device__ float g_K[B_*H_*L_*DH];            // [B,H,L,Dh]  tf32 after rope
__device__ float g_V[B_*H_*DH*L_];            // [B,H,Dh,L]  tf32 (transposed)
__device__ float g_Y[B_*L_*D_];               // [B,L,D]     tf32
__device__ float g_WT1[3*D_*D_];              // tf32(w_qkv^T)  [6144,2048]
__device__ float g_WT2[D_*D_];                // tf32(w_proj^T) [2048,2048]

// ---------------------------- helpers -------------------------------------
__device__ __forceinline__ float tf32r(float x) {
    uint32_t u; asm("cvt.rna.tf32.f32 %0, %1;" : "=r"(u) : "f"(x));
    return __uint_as_float(u);
}

__device__ __forceinline__ void mma_tf32(float* c, const uint32_t* a, const uint32_t* b) {
    asm volatile(
        "mma.sync.aligned.m16n8k8.row.col.f32.tf32.tf32.f32 "
        "{%0,%1,%2,%3},{%4,%5,%6,%7},{%8,%9},{%0,%1,%2,%3};\n"
        : "+f"(c[0]), "+f"(c[1]), "+f"(c[2]), "+f"(c[3])
        : "r"(a[0]), "r"(a[1]), "r"(a[2]), "r"(a[3]), "r"(b[0]), "r"(b[1]));
}

__device__ __forceinline__ void cp16(uint32_t s, const float* g) {
    asm volatile("cp.async.cg.shared.global [%0], [%1], 16;\n" :: "r"(s), "l"(g));
}

// ==== 128x256 CTA tile GEMM core, K-step 32, cp.async double-buffered =====
// A: [128,K] K-major (tf32 in gmem). B: [256 n-rows, K] K-major (tf32).
// 8 warps = 2m x 4n, each 64x64. acc[4][8][4].
__device__ __forceinline__ void gemm_core(
    const float* __restrict__ Ab, int lda,
    const float* __restrict__ Bb, int ldb,
    int kTiles, float (&acc)[4][8][4], float* smem)
{
    const int tid  = threadIdx.x;
    const int lane = tid & 31, warp = tid >> 5;
    const int wm = warp >> 2, wn = warp & 3;
    const int r = lane >> 2, c = lane & 3;
    const int r0 = tid >> 3, kc = tid & 7;
    uint32_t sbase = (uint32_t)__cvta_generic_to_shared(smem);

    const float* Asrc = Ab + (size_t)r0 * lda + kc * 4;
    const float* Bsrc = Bb + (size_t)r0 * ldb + kc * 4;
    const uint32_t dA0 = sbase + (r0 * GS + kc * 4) * 4;
    const uint32_t dB0 = sbase + (BOFF_F + r0 * GS + kc * 4) * 4;

#define ISSUE(kt, buf)                                                        \
    {                                                                         \
        const float* a_ = Asrc + (kt) * 32;                                   \
        const float* b_ = Bsrc + (kt) * 32;                                   \
        uint32_t da_ = dA0 + (buf) * (STAGE_F * 4);                           \
        uint32_t db_ = dB0 + (buf) * (STAGE_F * 4);                           \
        _Pragma("unroll") for (int i_ = 0; i_ < 4; i_++)                      \
            cp16(da_ + i_ * (32 * GS * 4), a_ + (size_t)i_ * 32 * lda);       \
        _Pragma("unroll") for (int i_ = 0; i_ < 8; i_++)                      \
            cp16(db_ + i_ * (32 * GS * 4), b_ + (size_t)i_ * 32 * ldb);       \
        asm volatile("cp.async.commit_group;\n");                             \
    }

    ISSUE(0, 0);
    for (int kt = 0; kt < kTiles; kt++) {
        int buf = kt & 1;
        if (kt + 1 < kTiles) {
            ISSUE(kt + 1, buf ^ 1);
            asm volatile("cp.async.wait_group 1;\n");
        } else {
            asm volatile("cp.async.wait_group 0;\n");
        }
        __syncthreads();
        const float* As = smem + buf * STAGE_F;
        const float* Bs = As + BOFF_F;
#pragma unroll
        for (int k0 = 0; k0 < 32; k0 += 8) {
            uint32_t af[4][4], bf[8][2];
#pragma unroll
            for (int mi = 0; mi < 4; mi++) {
                int row = wm * 64 + mi * 16 + r;
                af[mi][0] = __float_as_uint(As[row * GS + k0 + c]);
                af[mi][1] = __float_as_uint(As[(row + 8) * GS + k0 + c]);
                af[mi][2] = __float_as_uint(As[row * GS + k0 + c + 4]);
                af[mi][3] = __float_as_uint(As[(row + 8) * GS + k0 + c + 4]);
            }
#pragma unroll
            for (int ni = 0; ni < 8; ni++) {
                int col = wn * 64 + ni * 8 + r;
                bf[ni][0] = __float_as_uint(Bs[col * GS + k0 + c]);
                bf[ni][1] = __float_as_uint(Bs[col * GS + k0 + c + 4]);
            }
#pragma unroll
            for (int mi = 0; mi < 4; mi++)
#pragma unroll
                for (int ni = 0; ni < 8; ni++)
                    mma_tf32(acc[mi][ni], af[mi], bf[ni]);
        }
        __syncthreads();
    }
#undef ISSUE
}

#define ACC_ZERO8(acc)                                  \
    _Pragma("unroll") for (int _i = 0; _i < 4; _i++)    \
    _Pragma("unroll") for (int _j = 0; _j < 8; _j++)    \
    _Pragma("unroll") for (int _k = 0; _k < 4; _k++) acc[_i][_j][_k] = 0.f;

// -------------------- x -> tf32 convert ------------------------------------
__global__ __launch_bounds__(256) void k_cvt(const float4* __restrict__ src) {
    int i = blockIdx.x * 256 + threadIdx.x;
    float4 v = src[i];
    v.x = tf32r(v.x); v.y = tf32r(v.y); v.z = tf32r(v.z); v.w = tf32r(v.w);
    ((float4*)g_X)[i] = v;
}

// ----------------- weight transpose (+ tf32 convert) -----------------------
__global__ __launch_bounds__(256) void k_transpose(const float* __restrict__ src,
                                                   float* __restrict__ dst,
                                                   int R, int C) {
    __shared__ float t[32][33];
    int bx = blockIdx.x * 32, by = blockIdx.y * 32;
    int x = bx + threadIdx.x;
#pragma unroll
    for (int i = 0; i < 32; i += 8)
        t[threadIdx.y + i][threadIdx.x] = src[(size_t)(by + threadIdx.y + i) * C + x];
    __syncthreads();
    int x2 = by + threadIdx.x;
#pragma unroll
    for (int i = 0; i < 32; i += 8)
        dst[(size_t)(bx + threadIdx.y + i) * R + x2] = tf32r(t[threadIdx.x][threadIdx.y + i]);
}

// ============ GEMM 1: qkv = X @ WT1^T -> scatter Q/K/V ====================
__global__ __launch_bounds__(256, 1) void k_qkv() {
    extern __shared__ float sm[];
    const int bn = blockIdx.x, bm = blockIdx.y;
    float acc[4][8][4];
    ACC_ZERO8(acc);
    gemm_core(g_X + (size_t)bm * 128 * D_, D_,
              g_WT1 + (size_t)bn * 256 * D_, D_, D_ / 32, acc, sm);

    const int lane = threadIdx.x & 31, warp = threadIdx.x >> 5;
    const int wm = warp >> 2, wn = warp & 3;
#pragma unroll
    for (int mi = 0; mi < 4; mi++)
#pragma unroll
        for (int ni = 0; ni < 8; ni++)
#pragma unroll
            for (int rg = 0; rg < 4; rg++) {
                int row = wm * 64 + mi * 16 + (lane >> 2) + ((rg >> 1) ? 8 : 0);
                int col = wn * 64 + ni * 8 + 2 * (lane & 3) + (rg & 1);
                int m = bm * 128 + row, n = bn * 256 + col;
                int bb = m >> 11, l = m & 2047;
                int part = n >> 11, idx = n & 2047;
                int h = idx >> 7, d = idx & 127;
                float v = acc[mi][ni][rg];
                if (part == 2)
                    g_V[(((size_t)bb * H_ + h) * DH + d) * L_ + l] = tf32r(v);
                else if (part == 1)
                    g_K[(((size_t)bb * H_ + h) * L_ + l) * DH + d] = v;
                else
                    g_Q[(((size_t)bb * H_ + h) * L_ + l) * DH + d] = v;
            }
}

// ============ RoPE on Q and K, in place (writes tf32) =====================
__global__ void k_rope() {
    int idx = blockIdx.x * blockDim.x + threadIdx.x;
    int i   = idx & 63;
    int bhl = idx >> 6;
    int l   = bhl & 2047;
    float inv_freq = powf(10000.0f, -(float)(2 * i) * (1.0f / 128.0f));
    float ang = (float)l * inv_freq;
    float s, cc;
    sincosf(ang, &s, &cc);
    int base = bhl << 7;
    float q0 = g_Q[base + i], q1 = g_Q[base + i + 64];
    g_Q[base + i]      = tf32r(q0 * cc - q1 * s);
    g_Q[base + i + 64] = tf32r(q1 * cc + q0 * s);
    float k0 = g_K[base + i], k1 = g_K[base + i + 64];
    g_K[base + i]      = tf32r(k0 * cc - k1 * s);
    g_K[base + i + 64] = tf32r(k1 * cc + k0 * s);
}

// ======== fused flash attention: per (bh, 128-q-block) CTA ================
#define SM_Q   0
#define SM_K   (128*SMS)
#define SM_V   (2*128*SMS)
#define SM_R1  (3*128*SMS)
#define SM_R2  (SM_R1 + 512)
#define SM_AM  (SM_R2 + 512)
#define SM_TOT ((SM_AM + 128) * 4)

__global__ __launch_bounds__(256, 1) void k_attn(const int* __restrict__ amask) {
    extern __shared__ float sm[];
    float* Qs = sm + SM_Q;
    float* Ks = sm + SM_K;      // reused as Ps
    float* Vs = sm + SM_V;
    float* red1 = sm + SM_R1;
    float* red2 = sm + SM_R2;
    int*   am_s = (int*)(sm + SM_AM);

    const int bm = 15 - blockIdx.x;
    const int bh = blockIdx.y;
    const int bb = bh >> 4, hh = bh & 15;
    const int tid = threadIdx.x;
    const int lane = tid & 31, warp = tid >> 5;
    const int wm = warp >> 2, wn = warp & 3;
    const int r = lane >> 2, c = lane & 3;

    const float* Qg = g_Q + (size_t)bh * L_ * DH + (size_t)bm * 128 * DH;
#pragma unroll
    for (int i = 0; i < 16; i++) {
        int idx = i * 256 + tid;
        int row = idx >> 5, cg = (idx & 31) * 4;
        float4 v = *(const float4*)(Qg + (size_t)row * DH + cg);
        Qs[row * SMS + cg + 0] = tf32r(v.x * SCALE);
        Qs[row * SMS + cg + 1] = tf32r(v.y * SCALE);
        Qs[row * SMS + cg + 2] = tf32r(v.z * SCALE);
        Qs[row * SMS + cg + 3] = tf32r(v.w * SCALE);
    }

    float oacc[4][4][4];
#pragma unroll
    for (int _i = 0; _i < 4; _i++)
#pragma unroll
        for (int _j = 0; _j < 4; _j++)
#pragma unroll
            for (int _k = 0; _k < 4; _k++) oacc[_i][_j][_k] = 0.f;
    float mrow[4][2], lrow[4][2];
#pragma unroll
    for (int mi = 0; mi < 4; mi++)
#pragma unroll
        for (int h = 0; h < 2; h++) { mrow[mi][h] = -3.0e38f; lrow[mi][h] = 0.f; }

    for (int kb = 0; kb <= bm; kb++) {
        __syncthreads();
        const float* Kg = g_K + (size_t)bh * L_ * DH + (size_t)kb * 128 * DH;
        const float* Vg = g_V + (size_t)bh * DH * L_ + (size_t)kb * 128;
#pragma unroll
        for (int i = 0; i < 16; i++) {
            int idx = i * 256 + tid;
            int row = idx >> 5, cg = (idx & 31) * 4;
            *(float4*)&Ks[row * SMS + cg] = *(const float4*)(Kg + (size_t)row * DH + cg);
            *(float4*)&Vs[row * SMS + cg] = *(const float4*)(Vg + (size_t)row * L_ + cg);
        }
        if (tid < 128) am_s[tid] = amask[bb * L_ + kb * 128 + tid];
        __syncthreads();

        float sacc[4][4][4];
#pragma unroll
        for (int _i = 0; _i < 4; _i++)
#pragma unroll
            for (int _j = 0; _j < 4; _j++)
#pragma unroll
                for (int _k = 0; _k < 4; _k++) sacc[_i][_j][_k] = 0.f;
#pragma unroll
        for (int k0 = 0; k0 < 128; k0 += 8) {
            uint32_t af[4][4], bf[4][2];
#pragma unroll
            for (int mi = 0; mi < 4; mi++) {
                int row = wm * 64 + mi * 16 + r;
                af[mi][0] = __float_as_uint(Qs[row * SMS + k0 + c]);
                af[mi][1] = __float_as_uint(Qs[(row + 8) * SMS + k0 + c]);
                af[mi][2] = __float_as_uint(Qs[row * SMS + k0 + c + 4]);
                af[mi][3] = __float_as_uint(Qs[(row + 8) * SMS + k0 + c + 4]);
            }
#pragma unroll
            for (int ni = 0; ni < 4; ni++) {
                int col = wn * 32 + ni * 8 + r;
                bf[ni][0] = __float_as_uint(Ks[col * SMS + k0 + c]);
                bf[ni][1] = __float_as_uint(Ks[col * SMS + k0 + c + 4]);
            }
#pragma unroll
            for (int mi = 0; mi < 4; mi++)
#pragma unroll
                for (int ni = 0; ni < 4; ni++)
                    mma_tf32(sacc[mi][ni], af[mi], bf[ni]);
        }

        int amf[4][2];
#pragma unroll
        for (int ni = 0; ni < 4; ni++)
#pragma unroll
            for (int par = 0; par < 2; par++)
                amf[ni][par] = am_s[wn * 32 + ni * 8 + 2 * c + par];
        const bool diag = (kb == bm);
#pragma unroll
        for (int mi = 0; mi < 4; mi++)
#pragma unroll
            for (int ni = 0; ni < 4; ni++)
#pragma unroll
                for (int rg = 0; rg < 4; rg++) {
                    bool ok = amf[ni][rg & 1] != 0;
                    if (diag) {
                        int qr = bm * 128 + wm * 64 + mi * 16 + r + ((rg >> 1) ? 8 : 0);
                        int kc2 = kb * 128 + wn * 32 + ni * 8 + 2 * c + (rg & 1);
                        ok = ok && (kc2 <= qr);
                    }
                    if (!ok) sacc[mi][ni][rg] = NEGV;
                }

#pragma unroll
        for (int mi = 0; mi < 4; mi++)
#pragma unroll
            for (int h = 0; h < 2; h++) {
                float pm = -3.0e38f;
#pragma unroll
                for (int ni = 0; ni < 4; ni++)
                    pm = fmaxf(pm, fmaxf(sacc[mi][ni][2 * h], sacc[mi][ni][2 * h + 1]));
                pm = fmaxf(pm, __shfl_xor_sync(0xffffffff, pm, 1));
                pm = fmaxf(pm, __shfl_xor_sync(0xffffffff, pm, 2));
                if (c == 0)
                    red1[(wm * 64 + mi * 16 + r + 8 * h) * 4 + wn] = pm;
            }
        __syncthreads();

        float mnew[4][2], sfac[4][2];
#pragma unroll
        for (int mi = 0; mi < 4; mi++)
#pragma unroll
            for (int h = 0; h < 2; h++) {
                int row = wm * 64 + mi * 16 + r + 8 * h;
                float mb = fmaxf(fmaxf(red1[row * 4 + 0], red1[row * 4 + 1]),
                                 fmaxf(red1[row * 4 + 2], red1[row * 4 + 3]));
                float mn = fmaxf(mrow[mi][h], mb);
                sfac[mi][h] = __expf(mrow[mi][h] - mn);
                mnew[mi][h] = mn;
                mrow[mi][h] = mn;
            }

#pragma unroll
        for (int mi = 0; mi < 4; mi++)
#pragma unroll
            for (int h = 0; h < 2; h++) {
                float ps = 0.f;
#pragma unroll
                for (int ni = 0; ni < 4; ni++) {
                    float p0 = __expf(sacc[mi][ni][2 * h]     - mnew[mi][h]);
                    float p1 = __expf(sacc[mi][ni][2 * h + 1] - mnew[mi][h]);
                    sacc[mi][ni][2 * h]     = p0;
                    sacc[mi][ni][2 * h + 1] = p1;
                    ps += p0 + p1;
                    oacc[mi][ni][2 * h]     *= sfac[mi][h];
                    oacc[mi][ni][2 * h + 1] *= sfac[mi][h];
                }
                ps += __shfl_xor_sync(0xffffffff, ps, 1);
                ps += __shfl_xor_sync(0xffffffff, ps, 2);
                int row = wm * 64 + mi * 16 + r + 8 * h;
                if (c == 0) red2[row * 4 + wn] = ps;
                lrow[mi][h] *= sfac[mi][h];
#pragma unroll
                for (int ni = 0; ni < 4; ni++) {
                    float2 p2;
                    p2.x = tf32r(sacc[mi][ni][2 * h]);
                    p2.y = tf32r(sacc[mi][ni][2 * h + 1]);
                    *(float2*)&Ks[row * SMS + wn * 32 + ni * 8 + 2 * c] = p2;
                }
            }
        __syncthreads();

#pragma unroll
        for (int mi = 0; mi < 4; mi++)
#pragma unroll
            for (int h = 0; h < 2; h++) {
                int row = wm * 64 + mi * 16 + r + 8 * h;
                lrow[mi][h] += red2[row * 4 + 0] + red2[row * 4 + 1] +
                               red2[row * 4 + 2] + red2[row * 4 + 3];
            }

#pragma unroll
        for (int k0 = 0; k0 < 128; k0 += 8) {
            uint32_t af[4][4], bf[4][2];
#pragma unroll
            for (int mi = 0; mi < 4; mi++) {
                int row = wm * 64 + mi * 16 + r;
                af[mi][0] = __float_as_uint(Ks[row * SMS + k0 + c]);
                af[mi][1] = __float_as_uint(Ks[(row + 8) * SMS + k0 + c]);
                af[mi][2] = __float_as_uint(Ks[row * SMS + k0 + c + 4]);
                af[mi][3] = __float_as_uint(Ks[(row + 8) * SMS + k0 + c + 4]);
            }
#pragma unroll
            for (int ni = 0; ni < 4; ni++) {
                int col = wn * 32 + ni * 8 + r;
                bf[ni][0] = __float_as_uint(Vs[col * SMS + k0 + c]);
                bf[ni][1] = __float_as_uint(Vs[col * SMS + k0 + c + 4]);
            }
#pragma unroll
            for (int mi = 0; mi < 4; mi++)
#pragma unroll
                for (int ni = 0; ni < 4; ni++)
                    mma_tf32(oacc[mi][ni], af[mi], bf[ni]);
        }
    }

    // epilogue: O /= l, write tf32 to g_Y
#pragma unroll
    for (int mi = 0; mi < 4; mi++)
#pragma unroll
        for (int h = 0; h < 2; h++) {
            float inv = 1.0f / lrow[mi][h];
            int qg = bm * 128 + wm * 64 + mi * 16 + r + 8 * h;
#pragma unroll
            for (int ni = 0; ni < 4; ni++) {
                float2 o2;
                o2.x = tf32r(oacc[mi][ni][2 * h]     * inv);
                o2.y = tf32r(oacc[mi][ni][2 * h + 1] * inv);
                int col = hh * DH + wn * 32 + ni * 8 + 2 * c;
                *(float2*)&g_Y[(size_t)(bb * L_ + qg) * D_ + col] = o2;
            }
        }
}

// ================= GEMM 4: out = Y @ w_proj ===============================
__global__ __launch_bounds__(256, 1) void k_proj(float* __restrict__ out) {
    extern __shared__ float sm[];
    const int bn = blockIdx.x, bm = blockIdx.y;
    float acc[4][8][4];
    ACC_ZERO8(acc);
    gemm_core(g_Y + (size_t)bm * 128 * D_, D_,
              g_WT2 + (size_t)bn * 256 * D_, D_, D_ / 32, acc, sm);

    const int lane = threadIdx.x & 31, warp = threadIdx.x >> 5;
    const int wm = warp >> 2, wn = warp & 3;
#pragma unroll
    for (int mi = 0; mi < 4; mi++)
#pragma unroll
        for (int ni = 0; ni < 8; ni++)
#pragma unroll
            for (int rg = 0; rg < 4; rg++) {
                int row = wm * 64 + mi * 16 + (lane >> 2) + ((rg >> 1) ? 8 : 0);
                int col = wn * 64 + ni * 8 + 2 * (lane & 3) + (rg & 1);
                int m = bm * 128 + row, n = bn * 256 + col;
                out[(size_t)m * D_ + n] = acc[mi][ni][rg];
            }
}

// ============================== launcher ==================================
extern "C" void kernel_launch(void* const* d_in, const int* in_sizes, int n_in,
                              void* d_out, int out_size) {
    const float* x      = (const float*)d_in[0];
    const int*   amask  = (const int*)d_in[1];
    const float* w_qkv  = (const float*)d_in[2];
    const float* w_proj = (const float*)d_in[3];
    float* out = (float*)d_out;

    float* wt1; cudaGetSymbolAddress((void**)&wt1, g_WT1);
    float* wt2; cudaGetSymbolAddress((void**)&wt2, g_WT2);

    cudaFuncSetAttribute(k_qkv,  cudaFuncAttributeMaxDynamicSharedMemorySize, GEMM_SMEM);
    cudaFuncSetAttribute(k_proj, cudaFuncAttributeMaxDynamicSharedMemorySize, GEMM_SMEM);
    cudaFuncSetAttribute(k_attn, cudaFuncAttributeMaxDynamicSharedMemorySize, SM_TOT);

    k_cvt<<<(B_ * L_ * D_ / 4) / 256, 256>>>((const float4*)x);
    k_transpose<<<dim3(3 * D_ / 32, D_ / 32), dim3(32, 8)>>>(w_qkv, wt1, D_, 3 * D_);
    k_transpose<<<dim3(D_ / 32, D_ / 32), dim3(32, 8)>>>(w_proj, wt2, D_, D_);
    k_qkv<<<dim3(24, 32), 256, GEMM_SMEM>>>();
    k_rope<<<(B_ * H_ * L_ * 64) / 256, 256>>>();
    k_attn<<<dim3(16, 32), 256, SM_TOT>>>(amask);
    k_proj<<<dim3(8, 32), 256, GEMM_SMEM>>>(out);
}

// round 6
// speedup vs baseline: 6.4360x; 1.7949x over previous
#include <cuda_runtime.h>
#include <cuda_fp16.h>
#include <math.h>
#include <stdint.h>

#define B_  2
#define L_  2048
#define D_  2048
#define H_  16
#define DH  128
#define NEGV  (-1000000000.0f)
#define SCALE 0.08838834764831845f

// ---- fp16 GEMM config: CTA 128x256, k-chunk 64 halves (=128B rows) -------
#define KCH 64
#define KTH (D_ / KCH)        // 32
#define RS  72                // smem row stride in halves (144B)
#define A_H (128 * RS)        // 9216 halves per stage for A
#define STG_H (384 * RS)      // 27648 halves per stage (A+B)
#define STG_B (STG_H * 2)     // 55296 bytes
#define GEMM_SMEM (3 * STG_B) // 165888
// ---- attn smem ----
#define RSA 136               // attn row stride in halves (272B)
#define TILE_H (128 * RSA)    // 17408 halves
#define AT_RED1 (3 * TILE_H * 2)          // byte offset of red1
#define AT_RED2 (AT_RED1 + 2048)
#define AT_AM   (AT_RED2 + 2048)
#define ATTN_SMEM (AT_AM + 512)

// ---------------- scratch (device globals; no runtime allocation) ----------
__device__ __half g_Xh[B_*L_*D_];             // fp16(x)
__device__ __half g_Qh[B_*H_*L_*DH];          // [B,H,L,Dh] fp16, rope+scale
__device__ __half g_Kh[B_*H_*L_*DH];          // [B,H,L,Dh] fp16, rope
__device__ __half g_Vh[B_*H_*DH*L_];          // [B,H,Dh,L] fp16 (transposed)
__device__ __half g_Yh[B_*L_*D_];             // [B,L,D]    fp16
__device__ __half g_WT1h[3*D_*D_];            // fp16(w_qkv^T)  [6144,2048]
__device__ __half g_WT2h[D_*D_];              // fp16(w_proj^T) [2048,2048]

// ---------------------------- helpers -------------------------------------
__device__ __forceinline__ uint32_t smem_u32(const void* p) {
    uint32_t a;
    asm("{ .reg .u64 t; cvta.to.shared.u64 t, %1; cvt.u32.u64 %0, t; }"
        : "=r"(a) : "l"(p));
    return a;
}
__device__ __forceinline__ void cp16(uint32_t s, const void* g) {
    asm volatile("cp.async.cg.shared.global [%0], [%1], 16;\n" :: "r"(s), "l"(g));
}
template<int N> __device__ __forceinline__ void cpwait() {
    asm volatile("cp.async.wait_group %0;\n" :: "n"(N));
}
__device__ __forceinline__ void mma_f16(float* c, const uint32_t* a, const uint32_t* b) {
    asm volatile(
        "mma.sync.aligned.m16n8k16.row.col.f32.f16.f16.f32 "
        "{%0,%1,%2,%3},{%4,%5,%6,%7},{%8,%9},{%0,%1,%2,%3};\n"
        : "+f"(c[0]), "+f"(c[1]), "+f"(c[2]), "+f"(c[3])
        : "r"(a[0]), "r"(a[1]), "r"(a[2]), "r"(a[3]), "r"(b[0]), "r"(b[1]));
}
__device__ __forceinline__ uint32_t h2u(__half2 h) {
    return *reinterpret_cast<uint32_t*>(&h);
}

// ============ fp16 GEMM: C[128bm, 256bn] = A[.,2048] @ B^T ================
// EPI 0: qkv scatter (half) to g_Qh/g_Kh/g_Vh.  EPI 1: fp32 to out.
template<int EPI>
__global__ __launch_bounds__(256, 1) void k_gemm_h(const __half* __restrict__ A,
                                                   const __half* __restrict__ Bw,
                                                   float* __restrict__ out) {
    extern __shared__ __half smh[];
    const int tid = threadIdx.x, lane = tid & 31, warp = tid >> 5;
    const int wm = warp >> 2, wn = warp & 3;
    const int r = lane >> 2, qc = lane & 3;
    const int bn = blockIdx.x, bm = blockIdx.y;

    const int rA = tid >> 3, kg = tid & 7;
    const __half* srcA = A + (size_t)(bm * 128 + rA) * D_ + kg * 8;
    const __half* srcB = Bw + (size_t)(bn * 256 + rA) * D_ + kg * 8;
    const uint32_t sb = smem_u32(smh);
    const uint32_t dA = sb + rA * (RS * 2) + kg * 16;
    const uint32_t dB = sb + A_H * 2 + rA * (RS * 2) + kg * 16;

    float acc[4][8][4];
#pragma unroll
    for (int i = 0; i < 4; i++)
#pragma unroll
        for (int j = 0; j < 8; j++)
#pragma unroll
            for (int k = 0; k < 4; k++) acc[i][j][k] = 0.f;

#define ISSUE(cc)                                                             \
    { const uint32_t so_ = ((cc) % 3) * STG_B;                                \
      const int ko_ = (cc) * KCH;                                             \
      _Pragma("unroll") for (int i_ = 0; i_ < 4; i_++)                        \
          cp16(dA + so_ + i_ * (32 * RS * 2), srcA + ko_ + (size_t)i_ * 32 * D_); \
      _Pragma("unroll") for (int i_ = 0; i_ < 8; i_++)                        \
          cp16(dB + so_ + i_ * (32 * RS * 2), srcB + ko_ + (size_t)i_ * 32 * D_); \
      asm volatile("cp.async.commit_group;\n" ::: "memory"); }

    ISSUE(0); ISSUE(1);

    for (int ct = 0; ct < KTH; ct++) {
        if (ct < KTH - 1) cpwait<1>(); else cpwait<0>();
        __syncthreads();
        const __half* As = smh + (ct % 3) * STG_H;
        const __half* Bs = As + A_H;
#pragma unroll
        for (int k0 = 0; k0 < KCH; k0 += 16) {
            uint32_t af[4][4], bf[8][2];
#pragma unroll
            for (int mi = 0; mi < 4; mi++) {
                int row = wm * 64 + mi * 16 + r;
                af[mi][0] = *(const uint32_t*)&As[row * RS + k0 + 2 * qc];
                af[mi][1] = *(const uint32_t*)&As[(row + 8) * RS + k0 + 2 * qc];
                af[mi][2] = *(const uint32_t*)&As[row * RS + k0 + 2 * qc + 8];
                af[mi][3] = *(const uint32_t*)&As[(row + 8) * RS + k0 + 2 * qc + 8];
            }
#pragma unroll
            for (int ni = 0; ni < 8; ni++) {
                int col = wn * 64 + ni * 8 + r;
                bf[ni][0] = *(const uint32_t*)&Bs[col * RS + k0 + 2 * qc];
                bf[ni][1] = *(const uint32_t*)&Bs[col * RS + k0 + 2 * qc + 8];
            }
#pragma unroll
            for (int mi = 0; mi < 4; mi++)
#pragma unroll
                for (int ni = 0; ni < 8; ni++)
                    mma_f16(acc[mi][ni], af[mi], bf[ni]);
        }
        __syncthreads();
        if (ct + 2 < KTH) ISSUE(ct + 2);
    }
#undef ISSUE

    // ---- epilogue ----
#pragma unroll
    for (int mi = 0; mi < 4; mi++)
#pragma unroll
        for (int ni = 0; ni < 8; ni++)
#pragma unroll
            for (int rg = 0; rg < 4; rg++) {
                int row = wm * 64 + mi * 16 + r + ((rg >> 1) ? 8 : 0);
                int col = wn * 64 + ni * 8 + 2 * qc + (rg & 1);
                int m = bm * 128 + row, n = bn * 256 + col;
                float v = acc[mi][ni][rg];
                if (EPI == 1) {
                    out[(size_t)m * D_ + n] = v;
                } else {
                    int bb = m >> 11, l = m & 2047;
                    int part = n >> 11, idx = n & 2047;
                    int h = idx >> 7, d = idx & 127;
                    __half hv = __float2half_rn(v);
                    if (part == 2)
                        g_Vh[(((size_t)bb * H_ + h) * DH + d) * L_ + l] = hv;
                    else if (part == 1)
                        g_Kh[(((size_t)bb * H_ + h) * L_ + l) * DH + d] = hv;
                    else
                        g_Qh[(((size_t)bb * H_ + h) * L_ + l) * DH + d] = hv;
                }
            }
}

// -------------------- x -> fp16 convert ------------------------------------
__global__ __launch_bounds__(256) void k_cvt(const float4* __restrict__ src) {
    int i = blockIdx.x * 256 + threadIdx.x;
    float4 a = src[2 * i], b = src[2 * i + 1];
    uint4 o;
    o.x = h2u(__floats2half2_rn(a.x, a.y));
    o.y = h2u(__floats2half2_rn(a.z, a.w));
    o.z = h2u(__floats2half2_rn(b.x, b.y));
    o.w = h2u(__floats2half2_rn(b.z, b.w));
    ((uint4*)g_Xh)[i] = o;
}

// ----------------- weight transpose (+ fp16 convert) -----------------------
__global__ __launch_bounds__(256) void k_transpose(const float* __restrict__ src,
                                                   __half* __restrict__ dst,
                                                   int R, int C) {
    __shared__ float t[32][33];
    int bx = blockIdx.x * 32, by = blockIdx.y * 32;
    int x = bx + threadIdx.x;
#pragma unroll
    for (int i = 0; i < 32; i += 8)
        t[threadIdx.y + i][threadIdx.x] = src[(size_t)(by + threadIdx.y + i) * C + x];
    __syncthreads();
    int x2 = by + threadIdx.x;
#pragma unroll
    for (int i = 0; i < 32; i += 8)
        dst[(size_t)(bx + threadIdx.y + i) * R + x2] =
            __float2half_rn(t[threadIdx.x][threadIdx.y + i]);
}

// ==== RoPE on Q (folds SCALE) and K, in place, fp16 in/out ================
__global__ void k_rope() {
    int idx = blockIdx.x * blockDim.x + threadIdx.x;
    int i   = idx & 63;
    int bhl = idx >> 6;
    int l   = bhl & 2047;
    float inv_freq = powf(10000.0f, -(float)(2 * i) * (1.0f / 128.0f));
    float ang = (float)l * inv_freq;
    float s, cc;
    sincosf(ang, &s, &cc);
    int base = bhl << 7;
    float q0 = __half2float(g_Qh[base + i]), q1 = __half2float(g_Qh[base + i + 64]);
    g_Qh[base + i]      = __float2half_rn((q0 * cc - q1 * s) * SCALE);
    g_Qh[base + i + 64] = __float2half_rn((q1 * cc + q0 * s) * SCALE);
    float k0 = __half2float(g_Kh[base + i]), k1 = __half2float(g_Kh[base + i + 64]);
    g_Kh[base + i]      = __float2half_rn(k0 * cc - k1 * s);
    g_Kh[base + i + 64] = __float2half_rn(k1 * cc + k0 * s);
}

// ======== fused flash attention (fp16 mma): per (bh, 128-q-block) CTA =====
__global__ __launch_bounds__(256, 1) void k_attn(const int* __restrict__ amask) {
    extern __shared__ __half smh[];
    __half* Qs = smh;
    __half* Ks = smh + TILE_H;            // reused as Ps
    __half* Vs = smh + 2 * TILE_H;
    float* red1 = (float*)((char*)smh + AT_RED1);
    float* red2 = (float*)((char*)smh + AT_RED2);
    int*   am_s = (int*)((char*)smh + AT_AM);

    const int bm = 15 - blockIdx.x;
    const int bh = blockIdx.y;
    const int bb = bh >> 4, hh = bh & 15;
    const int tid = threadIdx.x;
    const int lane = tid & 31, warp = tid >> 5;
    const int wm = warp >> 2, wn = warp & 3;
    const int r = lane >> 2, qc = lane & 3;

    // --- load Q block (already scaled+roped fp16) ---
    const __half* Qg = g_Qh + (size_t)bh * L_ * DH + (size_t)bm * 128 * DH;
#pragma unroll
    for (int i = 0; i < 8; i++) {
        int g = i * 256 + tid;
        int row = g >> 4, kgg = g & 15;
        *(uint4*)&Qs[row * RSA + kgg * 8] = *(const uint4*)(Qg + row * DH + kgg * 8);
    }

    float oacc[4][4][4];
#pragma unroll
    for (int _i = 0; _i < 4; _i++)
#pragma unroll
        for (int _j = 0; _j < 4; _j++)
#pragma unroll
            for (int _k = 0; _k < 4; _k++) oacc[_i][_j][_k] = 0.f;
    float mrow[4][2], lrow[4][2];
#pragma unroll
    for (int mi = 0; mi < 4; mi++)
#pragma unroll
        for (int h = 0; h < 2; h++) { mrow[mi][h] = -3.0e38f; lrow[mi][h] = 0.f; }

    for (int kb = 0; kb <= bm; kb++) {
        __syncthreads();
        const __half* Kg = g_Kh + (size_t)bh * L_ * DH + (size_t)kb * 128 * DH;
        const __half* Vg = g_Vh + (size_t)bh * DH * L_ + (size_t)kb * 128;
#pragma unroll
        for (int i = 0; i < 8; i++) {
            int g = i * 256 + tid;
            int row = g >> 4, kgg = g & 15;
            *(uint4*)&Ks[row * RSA + kgg * 8] = *(const uint4*)(Kg + row * DH + kgg * 8);
            *(uint4*)&Vs[row * RSA + kgg * 8] = *(const uint4*)(Vg + (size_t)row * L_ + kgg * 8);
        }
        if (tid < 128) am_s[tid] = amask[bb * L_ + kb * 128 + tid];
        __syncthreads();

        // --- S = Q @ K^T ---
        float sacc[4][4][4];
#pragma unroll
        for (int _i = 0; _i < 4; _i++)
#pragma unroll
            for (int _j = 0; _j < 4; _j++)
#pragma unroll
                for (int _k = 0; _k < 4; _k++) sacc[_i][_j][_k] = 0.f;
#pragma unroll
        for (int k0 = 0; k0 < 128; k0 += 16) {
            uint32_t af[4][4], bf[4][2];
#pragma unroll
            for (int mi = 0; mi < 4; mi++) {
                int row = wm * 64 + mi * 16 + r;
                af[mi][0] = *(const uint32_t*)&Qs[row * RSA + k0 + 2 * qc];
                af[mi][1] = *(const uint32_t*)&Qs[(row + 8) * RSA + k0 + 2 * qc];
                af[mi][2] = *(const uint32_t*)&Qs[row * RSA + k0 + 2 * qc + 8];
                af[mi][3] = *(const uint32_t*)&Qs[(row + 8) * RSA + k0 + 2 * qc + 8];
            }
#pragma unroll
            for (int ni = 0; ni < 4; ni++) {
                int col = wn * 32 + ni * 8 + r;
                bf[ni][0] = *(const uint32_t*)&Ks[col * RSA + k0 + 2 * qc];
                bf[ni][1] = *(const uint32_t*)&Ks[col * RSA + k0 + 2 * qc + 8];
            }
#pragma unroll
            for (int mi = 0; mi < 4; mi++)
#pragma unroll
                for (int ni = 0; ni < 4; ni++)
                    mma_f16(sacc[mi][ni], af[mi], bf[ni]);
        }

        // --- mask ---
        int amf[4][2];
#pragma unroll
        for (int ni = 0; ni < 4; ni++)
#pragma unroll
            for (int par = 0; par < 2; par++)
                amf[ni][par] = am_s[wn * 32 + ni * 8 + 2 * qc + par];
        const bool diag = (kb == bm);
#pragma unroll
        for (int mi = 0; mi < 4; mi++)
#pragma unroll
            for (int ni = 0; ni < 4; ni++)
#pragma unroll
                for (int rg = 0; rg < 4; rg++) {
                    bool ok = amf[ni][rg & 1] != 0;
                    if (diag) {
                        int qr = bm * 128 + wm * 64 + mi * 16 + r + ((rg >> 1) ? 8 : 0);
                        int kc2 = kb * 128 + wn * 32 + ni * 8 + 2 * qc + (rg & 1);
                        ok = ok && (kc2 <= qr);
                    }
                    if (!ok) sacc[mi][ni][rg] = NEGV;
                }

        // --- rowmax ---
#pragma unroll
        for (int mi = 0; mi < 4; mi++)
#pragma unroll
            for (int h = 0; h < 2; h++) {
                float pm = -3.0e38f;
#pragma unroll
                for (int ni = 0; ni < 4; ni++)
                    pm = fmaxf(pm, fmaxf(sacc[mi][ni][2 * h], sacc[mi][ni][2 * h + 1]));
                pm = fmaxf(pm, __shfl_xor_sync(0xffffffff, pm, 1));
                pm = fmaxf(pm, __shfl_xor_sync(0xffffffff, pm, 2));
                if (qc == 0)
                    red1[(wm * 64 + mi * 16 + r + 8 * h) * 4 + wn] = pm;
            }
        __syncthreads();

        float mnew[4][2], sfac[4][2];
#pragma unroll
        for (int mi = 0; mi < 4; mi++)
#pragma unroll
            for (int h = 0; h < 2; h++) {
                int row = wm * 64 + mi * 16 + r + 8 * h;
                float mb = fmaxf(fmaxf(red1[row * 4 + 0], red1[row * 4 + 1]),
                                 fmaxf(red1[row * 4 + 2], red1[row * 4 + 3]));
                float mn = fmaxf(mrow[mi][h], mb);
                sfac[mi][h] = __expf(mrow[mi][h] - mn);
                mnew[mi][h] = mn;
                mrow[mi][h] = mn;
            }

        // --- exp, partial sums, rescale O, store P (half) into Ks ---
#pragma unroll
        for (int mi = 0; mi < 4; mi++)
#pragma unroll
            for (int h = 0; h < 2; h++) {
                float ps = 0.f;
#pragma unroll
                for (int ni = 0; ni < 4; ni++) {
                    float p0 = __expf(sacc[mi][ni][2 * h]     - mnew[mi][h]);
                    float p1 = __expf(sacc[mi][ni][2 * h + 1] - mnew[mi][h]);
                    sacc[mi][ni][2 * h]     = p0;
                    sacc[mi][ni][2 * h + 1] = p1;
                    ps += p0 + p1;
                    oacc[mi][ni][2 * h]     *= sfac[mi][h];
                    oacc[mi][ni][2 * h + 1] *= sfac[mi][h];
                }
                ps += __shfl_xor_sync(0xffffffff, ps, 1);
                ps += __shfl_xor_sync(0xffffffff, ps, 2);
                int row = wm * 64 + mi * 16 + r + 8 * h;
                if (qc == 0) red2[row * 4 + wn] = ps;
                lrow[mi][h] *= sfac[mi][h];
#pragma unroll
                for (int ni = 0; ni < 4; ni++)
                    *(__half2*)&Ks[row * RSA + wn * 32 + ni * 8 + 2 * qc] =
                        __floats2half2_rn(sacc[mi][ni][2 * h], sacc[mi][ni][2 * h + 1]);
            }
        __syncthreads();

#pragma unroll
        for (int mi = 0; mi < 4; mi++)
#pragma unroll
            for (int h = 0; h < 2; h++) {
                int row = wm * 64 + mi * 16 + r + 8 * h;
                lrow[mi][h] += red2[row * 4 + 0] + red2[row * 4 + 1] +
                               red2[row * 4 + 2] + red2[row * 4 + 3];
            }

        // --- O += P @ V ---
#pragma unroll
        for (int k0 = 0; k0 < 128; k0 += 16) {
            uint32_t af[4][4], bf[4][2];
#pragma unroll
            for (int mi = 0; mi < 4; mi++) {
                int row = wm * 64 + mi * 16 + r;
                af[mi][0] = *(const uint32_t*)&Ks[row * RSA + k0 + 2 * qc];
                af[mi][1] = *(const uint32_t*)&Ks[(row + 8) * RSA + k0 + 2 * qc];
                af[mi][2] = *(const uint32_t*)&Ks[row * RSA + k0 + 2 * qc + 8];
                af[mi][3] = *(const uint32_t*)&Ks[(row + 8) * RSA + k0 + 2 * qc + 8];
            }
#pragma unroll
            for (int ni = 0; ni < 4; ni++) {
                int col = wn * 32 + ni * 8 + r;
                bf[ni][0] = *(const uint32_t*)&Vs[col * RSA + k0 + 2 * qc];
                bf[ni][1] = *(const uint32_t*)&Vs[col * RSA + k0 + 2 * qc + 8];
            }
#pragma unroll
            for (int mi = 0; mi < 4; mi++)
#pragma unroll
                for (int ni = 0; ni < 4; ni++)
                    mma_f16(oacc[mi][ni], af[mi], bf[ni]);
        }
    }

    // --- epilogue: O /= l, write half to g_Yh ---
#pragma unroll
    for (int mi = 0; mi < 4; mi++)
#pragma unroll
        for (int h = 0; h < 2; h++) {
            float inv = 1.0f / lrow[mi][h];
            int qg = bm * 128 + wm * 64 + mi * 16 + r + 8 * h;
#pragma unroll
            for (int ni = 0; ni < 4; ni++) {
                int col = hh * DH + wn * 32 + ni * 8 + 2 * qc;
                *(__half2*)&g_Yh[(size_t)(bb * L_ + qg) * D_ + col] =
                    __floats2half2_rn(oacc[mi][ni][2 * h] * inv,
                                      oacc[mi][ni][2 * h + 1] * inv);
            }
        }
}

// ============================== launcher ==================================
extern "C" void kernel_launch(void* const* d_in, const int* in_sizes, int n_in,
                              void* d_out, int out_size) {
    const float* x      = (const float*)d_in[0];
    const int*   amask  = (const int*)d_in[1];
    const float* w_qkv  = (const float*)d_in[2];
    const float* w_proj = (const float*)d_in[3];
    float* out = (float*)d_out;

    __half* wt1; cudaGetSymbolAddress((void**)&wt1, g_WT1h);
    __half* wt2; cudaGetSymbolAddress((void**)&wt2, g_WT2h);
    __half* gx;  cudaGetSymbolAddress((void**)&gx, g_Xh);
    __half* gy;  cudaGetSymbolAddress((void**)&gy, g_Yh);

    cudaFuncSetAttribute(k_gemm_h<0>, cudaFuncAttributeMaxDynamicSharedMemorySize, GEMM_SMEM);
    cudaFuncSetAttribute(k_gemm_h<1>, cudaFuncAttributeMaxDynamicSharedMemorySize, GEMM_SMEM);
    cudaFuncSetAttribute(k_attn, cudaFuncAttributeMaxDynamicSharedMemorySize, ATTN_SMEM);

    k_cvt<<<(B_ * L_ * D_ / 8) / 256, 256>>>((const float4*)x);
    k_transpose<<<dim3(3 * D_ / 32, D_ / 32), dim3(32, 8)>>>(w_qkv, wt1, D_, 3 * D_);
    k_transpose<<<dim3(D_ / 32, D_ / 32), dim3(32, 8)>>>(w_proj, wt2, D_, D_);
    k_gemm_h<0><<<dim3(3 * D_ / 256, B_ * L_ / 128), 256, GEMM_SMEM>>>(gx, wt1, nullptr);
    k_rope<<<(B_ * H_ * L_ * 64) / 256, 256>>>();
    k_attn<<<dim3(16, 32), 256, ATTN_SMEM>>>(amask);
    k_gemm_h<1><<<dim3(D_ / 256, B_ * L_ / 128), 256, GEMM_SMEM>>>(gy, wt2, out);
}

// round 7
// speedup vs baseline: 6.5446x; 1.0169x over previous
#include <cuda_runtime.h>
#include <cuda_fp16.h>
#include <math.h>
#include <stdint.h>

#define B_  2
#define L_  2048
#define D_  2048
#define H_  16
#define DH  128
#define NEGV  (-1000000000.0f)
#define SCALE 0.08838834764831845f

// ---- fp16 GEMM config: CTA 128x256, k-chunk 64 halves (=128B rows) -------
#define KCH 64
#define KTH (D_ / KCH)        // 32
#define RS  72                // smem row stride in halves (144B)
#define A_H (128 * RS)
#define STG_H (384 * RS)
#define STG_B (STG_H * 2)
#define GEMM_SMEM (3 * STG_B)
// ---- attn smem ----
#define RSA 136               // attn row stride in halves (272B)
#define TILE_H (128 * RSA)
#define AT_RED1 (3 * TILE_H * 2)
#define AT_RED2 (AT_RED1 + 2048)
#define AT_AM   (AT_RED2 + 2048)
#define ATTN_SMEM (AT_AM + 512)

// ---------------- scratch (device globals; no runtime allocation) ----------
__device__ __half g_Xh[B_*L_*D_];
__device__ __half g_Qh[B_*H_*L_*DH];          // [B,H,L,Dh] fp16, rope+scale
__device__ __half g_Kh[B_*H_*L_*DH];          // [B,H,L,Dh] fp16, rope
__device__ __half g_Vh[B_*H_*DH*L_];          // [B,H,Dh,L] fp16 (transposed)
__device__ __half g_Yh[B_*L_*D_];
__device__ __half g_WT1h[3*D_*D_];            // fp16(w_qkv^T)
__device__ __half g_WT2h[D_*D_];              // fp16(w_proj^T)

// ---------------------------- helpers -------------------------------------
__device__ __forceinline__ uint32_t smem_u32(const void* p) {
    uint32_t a;
    asm("{ .reg .u64 t; cvta.to.shared.u64 t, %1; cvt.u32.u64 %0, t; }"
        : "=r"(a) : "l"(p));
    return a;
}
__device__ __forceinline__ void cp16(uint32_t s, const void* g) {
    asm volatile("cp.async.cg.shared.global [%0], [%1], 16;\n" :: "r"(s), "l"(g));
}
template<int N> __device__ __forceinline__ void cpwait() {
    asm volatile("cp.async.wait_group %0;\n" :: "n"(N));
}
__device__ __forceinline__ void mma_f16(float* c, const uint32_t* a, const uint32_t* b) {
    asm volatile(
        "mma.sync.aligned.m16n8k16.row.col.f32.f16.f16.f32 "
        "{%0,%1,%2,%3},{%4,%5,%6,%7},{%8,%9},{%0,%1,%2,%3};\n"
        : "+f"(c[0]), "+f"(c[1]), "+f"(c[2]), "+f"(c[3])
        : "r"(a[0]), "r"(a[1]), "r"(a[2]), "r"(a[3]), "r"(b[0]), "r"(b[1]));
}
__device__ __forceinline__ void ldsm4(uint32_t& r0, uint32_t& r1, uint32_t& r2,
                                      uint32_t& r3, uint32_t a) {
    asm volatile("ldmatrix.sync.aligned.m8n8.x4.shared.b16 {%0,%1,%2,%3}, [%4];"
                 : "=r"(r0), "=r"(r1), "=r"(r2), "=r"(r3) : "r"(a));
}
__device__ __forceinline__ uint32_t h2u(__half2 h) {
    return *reinterpret_cast<uint32_t*>(&h);
}

// ============ fp16 GEMM: C[128bm, 256bn] = A[.,2048] @ B^T ================
template<int EPI>
__global__ __launch_bounds__(256, 1) void k_gemm_h(const __half* __restrict__ A,
                                                   const __half* __restrict__ Bw,
                                                   float* __restrict__ out) {
    extern __shared__ __half smh[];
    const int tid = threadIdx.x, lane = tid & 31, warp = tid >> 5;
    const int wm = warp >> 2, wn = warp & 3;
    const int r = lane >> 2, qc = lane & 3;
    const int bn = blockIdx.x, bm = blockIdx.y;

    const int rA = tid >> 3, kg = tid & 7;
    const __half* srcA = A + (size_t)(bm * 128 + rA) * D_ + kg * 8;
    const __half* srcB = Bw + (size_t)(bn * 256 + rA) * D_ + kg * 8;
    const uint32_t sb = smem_u32(smh);
    const uint32_t dA = sb + rA * (RS * 2) + kg * 16;
    const uint32_t dB = sb + A_H * 2 + rA * (RS * 2) + kg * 16;

    // ldmatrix lane base addresses (byte offsets)
    const uint32_t aBase = sb + ((wm * 64 + (lane & 15)) * RS + (lane >> 4) * 8) * 2;
    const uint32_t bBase = sb + A_H * 2 +
        ((wn * 64 + (lane >> 4) * 8 + (lane & 7)) * RS + ((lane >> 3) & 1) * 8) * 2;

    float acc[4][8][4];
#pragma unroll
    for (int i = 0; i < 4; i++)
#pragma unroll
        for (int j = 0; j < 8; j++)
#pragma unroll
            for (int k = 0; k < 4; k++) acc[i][j][k] = 0.f;

#define ISSUE(cc)                                                             \
    { const uint32_t so_ = ((cc) % 3) * STG_B;                                \
      const int ko_ = (cc) * KCH;                                             \
      _Pragma("unroll") for (int i_ = 0; i_ < 4; i_++)                        \
          cp16(dA + so_ + i_ * (32 * RS * 2), srcA + ko_ + (size_t)i_ * 32 * D_); \
      _Pragma("unroll") for (int i_ = 0; i_ < 8; i_++)                        \
          cp16(dB + so_ + i_ * (32 * RS * 2), srcB + ko_ + (size_t)i_ * 32 * D_); \
      asm volatile("cp.async.commit_group;\n" ::: "memory"); }

    ISSUE(0); ISSUE(1);

    for (int ct = 0; ct < KTH; ct++) {
        if (ct < KTH - 1) cpwait<1>(); else cpwait<0>();
        __syncthreads();
        if (ct + 2 < KTH) ISSUE(ct + 2);   // stage (ct+2)%3 free after this sync
        const uint32_t so = (ct % 3) * STG_B;
#pragma unroll
        for (int k0 = 0; k0 < KCH; k0 += 16) {
            uint32_t af[4][4], bf[8][2];
#pragma unroll
            for (int mi = 0; mi < 4; mi++)
                ldsm4(af[mi][0], af[mi][1], af[mi][2], af[mi][3],
                      aBase + so + (mi * 16 * RS + k0) * 2);
#pragma unroll
            for (int p = 0; p < 4; p++)
                ldsm4(bf[2*p][0], bf[2*p][1], bf[2*p+1][0], bf[2*p+1][1],
                      bBase + so + (p * 16 * RS + k0) * 2);
#pragma unroll
            for (int mi = 0; mi < 4; mi++)
#pragma unroll
                for (int ni = 0; ni < 8; ni++)
                    mma_f16(acc[mi][ni], af[mi], bf[ni]);
        }
    }
#undef ISSUE

    // ---- epilogue ----
#pragma unroll
    for (int mi = 0; mi < 4; mi++)
#pragma unroll
        for (int ni = 0; ni < 8; ni++)
#pragma unroll
            for (int rg = 0; rg < 4; rg++) {
                int row = wm * 64 + mi * 16 + r + ((rg >> 1) ? 8 : 0);
                int col = wn * 64 + ni * 8 + 2 * qc + (rg & 1);
                int m = bm * 128 + row, n = bn * 256 + col;
                float v = acc[mi][ni][rg];
                if (EPI == 1) {
                    out[(size_t)m * D_ + n] = v;
                } else {
                    int bb = m >> 11, l = m & 2047;
                    int part = n >> 11, idx = n & 2047;
                    int h = idx >> 7, d = idx & 127;
                    __half hv = __float2half_rn(v);
                    if (part == 2)
                        g_Vh[(((size_t)bb * H_ + h) * DH + d) * L_ + l] = hv;
                    else if (part == 1)
                        g_Kh[(((size_t)bb * H_ + h) * L_ + l) * DH + d] = hv;
                    else
                        g_Qh[(((size_t)bb * H_ + h) * L_ + l) * DH + d] = hv;
                }
            }
}

// -------------------- x -> fp16 convert ------------------------------------
__global__ __launch_bounds__(256) void k_cvt(const float4* __restrict__ src) {
    int i = blockIdx.x * 256 + threadIdx.x;
    float4 a = src[2 * i], b = src[2 * i + 1];
    uint4 o;
    o.x = h2u(__floats2half2_rn(a.x, a.y));
    o.y = h2u(__floats2half2_rn(a.z, a.w));
    o.z = h2u(__floats2half2_rn(b.x, b.y));
    o.w = h2u(__floats2half2_rn(b.z, b.w));
    ((uint4*)g_Xh)[i] = o;
}

// ----------------- weight transpose (+ fp16 convert) -----------------------
__global__ __launch_bounds__(256) void k_transpose(const float* __restrict__ src,
                                                   __half* __restrict__ dst,
                                                   int R, int C) {
    __shared__ float t[32][33];
    int bx = blockIdx.x * 32, by = blockIdx.y * 32;
    int x = bx + threadIdx.x;
#pragma unroll
    for (int i = 0; i < 32; i += 8)
        t[threadIdx.y + i][threadIdx.x] = src[(size_t)(by + threadIdx.y + i) * C + x];
    __syncthreads();
    int x2 = by + threadIdx.x;
#pragma unroll
    for (int i = 0; i < 32; i += 8)
        dst[(size_t)(bx + threadIdx.y + i) * R + x2] =
            __float2half_rn(t[threadIdx.x][threadIdx.y + i]);
}

// ==== RoPE on Q (folds SCALE) and K, in place, fp16 in/out ================
__global__ void k_rope() {
    int idx = blockIdx.x * blockDim.x + threadIdx.x;
    int i   = idx & 63;
    int bhl = idx >> 6;
    int l   = bhl & 2047;
    float inv_freq = powf(10000.0f, -(float)(2 * i) * (1.0f / 128.0f));
    float ang = (float)l * inv_freq;
    float s, cc;
    sincosf(ang, &s, &cc);
    int base = bhl << 7;
    float q0 = __half2float(g_Qh[base + i]), q1 = __half2float(g_Qh[base + i + 64]);
    g_Qh[base + i]      = __float2half_rn((q0 * cc - q1 * s) * SCALE);
    g_Qh[base + i + 64] = __float2half_rn((q1 * cc + q0 * s) * SCALE);
    float k0 = __half2float(g_Kh[base + i]), k1 = __half2float(g_Kh[base + i + 64]);
    g_Kh[base + i]      = __float2half_rn(k0 * cc - k1 * s);
    g_Kh[base + i + 64] = __float2half_rn(k1 * cc + k0 * s);
}

// ======== fused flash attention (fp16 mma + ldmatrix) =====================
__global__ __launch_bounds__(256, 1) void k_attn(const int* __restrict__ amask) {
    extern __shared__ __half smh[];
    __half* Qs = smh;
    __half* Ks = smh + TILE_H;            // reused as Ps
    __half* Vs = smh + 2 * TILE_H;
    float* red1 = (float*)((char*)smh + AT_RED1);
    float* red2 = (float*)((char*)smh + AT_RED2);
    int*   am_s = (int*)((char*)smh + AT_AM);

    const int bm = 15 - blockIdx.x;
    const int bh = blockIdx.y;
    const int bb = bh >> 4, hh = bh & 15;
    const int tid = threadIdx.x;
    const int lane = tid & 31, warp = tid >> 5;
    const int wm = warp >> 2, wn = warp & 3;
    const int r = lane >> 2, qc = lane & 3;

    const uint32_t usb = smem_u32(smh);
    // ldmatrix lane bases: A-style (Q/P rows), B-style (K/V 32-col warp tiles)
    const uint32_t aOff = ((wm * 64 + (lane & 15)) * RSA + (lane >> 4) * 8) * 2;
    const uint32_t bOff = ((wn * 32 + (lane >> 4) * 8 + (lane & 7)) * RSA +
                           ((lane >> 3) & 1) * 8) * 2;
    const uint32_t qA = usb + aOff;
    const uint32_t kB = usb + TILE_H * 2 + bOff;
    const uint32_t pA = usb + TILE_H * 2 + aOff;
    const uint32_t vB = usb + 2 * TILE_H * 2 + bOff;

    // --- load Q block (already scaled+roped fp16) ---
    const __half* Qg = g_Qh + (size_t)bh * L_ * DH + (size_t)bm * 128 * DH;
#pragma unroll
    for (int i = 0; i < 8; i++) {
        int g = i * 256 + tid;
        int row = g >> 4, kgg = g & 15;
        *(uint4*)&Qs[row * RSA + kgg * 8] = *(const uint4*)(Qg + row * DH + kgg * 8);
    }

    float oacc[4][4][4];
#pragma unroll
    for (int _i = 0; _i < 4; _i++)
#pragma unroll
        for (int _j = 0; _j < 4; _j++)
#pragma unroll
            for (int _k = 0; _k < 4; _k++) oacc[_i][_j][_k] = 0.f;
    float mrow[4][2], lrow[4][2];
#pragma unroll
    for (int mi = 0; mi < 4; mi++)
#pragma unroll
        for (int h = 0; h < 2; h++) { mrow[mi][h] = -3.0e38f; lrow[mi][h] = 0.f; }

    for (int kb = 0; kb <= bm; kb++) {
        __syncthreads();
        const __half* Kg = g_Kh + (size_t)bh * L_ * DH + (size_t)kb * 128 * DH;
        const __half* Vg = g_Vh + (size_t)bh * DH * L_ + (size_t)kb * 128;
#pragma unroll
        for (int i = 0; i < 8; i++) {
            int g = i * 256 + tid;
            int row = g >> 4, kgg = g & 15;
            *(uint4*)&Ks[row * RSA + kgg * 8] = *(const uint4*)(Kg + row * DH + kgg * 8);
            *(uint4*)&Vs[row * RSA + kgg * 8] = *(const uint4*)(Vg + (size_t)row * L_ + kgg * 8);
        }
        if (tid < 128) am_s[tid] = amask[bb * L_ + kb * 128 + tid];
        __syncthreads();

        // --- S = Q @ K^T ---
        float sacc[4][4][4];
#pragma unroll
        for (int _i = 0; _i < 4; _i++)
#pragma unroll
            for (int _j = 0; _j < 4; _j++)
#pragma unroll
                for (int _k = 0; _k < 4; _k++) sacc[_i][_j][_k] = 0.f;
#pragma unroll
        for (int k0 = 0; k0 < 128; k0 += 16) {
            uint32_t af[4][4], bf[4][2];
#pragma unroll
            for (int mi = 0; mi < 4; mi++)
                ldsm4(af[mi][0], af[mi][1], af[mi][2], af[mi][3],
                      qA + (mi * 16 * RSA + k0) * 2);
#pragma unroll
            for (int p = 0; p < 2; p++)
                ldsm4(bf[2*p][0], bf[2*p][1], bf[2*p+1][0], bf[2*p+1][1],
                      kB + (p * 16 * RSA + k0) * 2);
#pragma unroll
            for (int mi = 0; mi < 4; mi++)
#pragma unroll
                for (int ni = 0; ni < 4; ni++)
                    mma_f16(sacc[mi][ni], af[mi], bf[ni]);
        }

        // --- mask ---
        int amf[4][2];
#pragma unroll
        for (int ni = 0; ni < 4; ni++)
#pragma unroll
            for (int par = 0; par < 2; par++)
                amf[ni][par] = am_s[wn * 32 + ni * 8 + 2 * qc + par];
        const bool diag = (kb == bm);
#pragma unroll
        for (int mi = 0; mi < 4; mi++)
#pragma unroll
            for (int ni = 0; ni < 4; ni++)
#pragma unroll
                for (int rg = 0; rg < 4; rg++) {
                    bool ok = amf[ni][rg & 1] != 0;
                    if (diag) {
                        int qr = bm * 128 + wm * 64 + mi * 16 + r + ((rg >> 1) ? 8 : 0);
                        int kc2 = kb * 128 + wn * 32 + ni * 8 + 2 * qc + (rg & 1);
                        ok = ok && (kc2 <= qr);
                    }
                    if (!ok) sacc[mi][ni][rg] = NEGV;
                }

        // --- rowmax ---
#pragma unroll
        for (int mi = 0; mi < 4; mi++)
#pragma unroll
            for (int h = 0; h < 2; h++) {
                float pm = -3.0e38f;
#pragma unroll
                for (int ni = 0; ni < 4; ni++)
                    pm = fmaxf(pm, fmaxf(sacc[mi][ni][2 * h], sacc[mi][ni][2 * h + 1]));
                pm = fmaxf(pm, __shfl_xor_sync(0xffffffff, pm, 1));
                pm = fmaxf(pm, __shfl_xor_sync(0xffffffff, pm, 2));
                if (qc == 0)
                    red1[(wm * 64 + mi * 16 + r + 8 * h) * 4 + wn] = pm;
            }
        __syncthreads();

        float mnew[4][2], sfac[4][2];
#pragma unroll
        for (int mi = 0; mi < 4; mi++)
#pragma unroll
            for (int h = 0; h < 2; h++) {
                int row = wm * 64 + mi * 16 + r + 8 * h;
                float mb = fmaxf(fmaxf(red1[row * 4 + 0], red1[row * 4 + 1]),
                                 fmaxf(red1[row * 4 + 2], red1[row * 4 + 3]));
                float mn = fmaxf(mrow[mi][h], mb);
                sfac[mi][h] = __expf(mrow[mi][h] - mn);
                mnew[mi][h] = mn;
                mrow[mi][h] = mn;
            }

        // --- exp, partial sums, rescale O, store P (half) into Ks ---
#pragma unroll
        for (int mi = 0; mi < 4; mi++)
#pragma unroll
            for (int h = 0; h < 2; h++) {
                float ps = 0.f;
#pragma unroll
                for (int ni = 0; ni < 4; ni++) {
                    float p0 = __expf(sacc[mi][ni][2 * h]     - mnew[mi][h]);
                    float p1 = __expf(sacc[mi][ni][2 * h + 1] - mnew[mi][h]);
                    sacc[mi][ni][2 * h]     = p0;
                    sacc[mi][ni][2 * h + 1] = p1;
                    ps += p0 + p1;
                    oacc[mi][ni][2 * h]     *= sfac[mi][h];
                    oacc[mi][ni][2 * h + 1] *= sfac[mi][h];
                }
                ps += __shfl_xor_sync(0xffffffff, ps, 1);
                ps += __shfl_xor_sync(0xffffffff, ps, 2);
                int row = wm * 64 + mi * 16 + r + 8 * h;
                if (qc == 0) red2[row * 4 + wn] = ps;
                lrow[mi][h] *= sfac[mi][h];
#pragma unroll
                for (int ni = 0; ni < 4; ni++)
                    *(__half2*)&Ks[row * RSA + wn * 32 + ni * 8 + 2 * qc] =
                        __floats2half2_rn(sacc[mi][ni][2 * h], sacc[mi][ni][2 * h + 1]);
            }
        __syncthreads();

#pragma unroll
        for (int mi = 0; mi < 4; mi++)
#pragma unroll
            for (int h = 0; h < 2; h++) {
                int row = wm * 64 + mi * 16 + r + 8 * h;
                lrow[mi][h] += red2[row * 4 + 0] + red2[row * 4 + 1] +
                               red2[row * 4 + 2] + red2[row * 4 + 3];
            }

        // --- O += P @ V ---
#pragma unroll
        for (int k0 = 0; k0 < 128; k0 += 16) {
            uint32_t af[4][4], bf[4][2];
#pragma unroll
            for (int mi = 0; mi < 4; mi++)
                ldsm4(af[mi][0], af[mi][1], af[mi][2], af[mi][3],
                      pA + (mi * 16 * RSA + k0) * 2);
#pragma unroll
            for (int p = 0; p < 2; p++)
                ldsm4(bf[2*p][0], bf[2*p][1], bf[2*p+1][0], bf[2*p+1][1],
                      vB + (p * 16 * RSA + k0) * 2);
#pragma unroll
            for (int mi = 0; mi < 4; mi++)
#pragma unroll
                for (int ni = 0; ni < 4; ni++)
                    mma_f16(oacc[mi][ni], af[mi], bf[ni]);
        }
    }

    // --- epilogue: O /= l, write half to g_Yh ---
#pragma unroll
    for (int mi = 0; mi < 4; mi++)
#pragma unroll
        for (int h = 0; h < 2; h++) {
            float inv = 1.0f / lrow[mi][h];
            int qg = bm * 128 + wm * 64 + mi * 16 + r + 8 * h;
#pragma unroll
            for (int ni = 0; ni < 4; ni++) {
                int col = hh * DH + wn * 32 + ni * 8 + 2 * qc;
                *(__half2*)&g_Yh[(size_t)(bb * L_ + qg) * D_ + col] =
                    __floats2half2_rn(oacc[mi][ni][2 * h] * inv,
                                      oacc[mi][ni][2 * h + 1] * inv);
            }
        }
}

// ============================== launcher ==================================
extern "C" void kernel_launch(void* const* d_in, const int* in_sizes, int n_in,
                              void* d_out, int out_size) {
    const float* x      = (const float*)d_in[0];
    const int*   amask  = (const int*)d_in[1];
    const float* w_qkv  = (const float*)d_in[2];
    const float* w_proj = (const float*)d_in[3];
    float* out = (float*)d_out;

    __half* wt1; cudaGetSymbolAddress((void**)&wt1, g_WT1h);
    __half* wt2; cudaGetSymbolAddress((void**)&wt2, g_WT2h);
    __half* gx;  cudaGetSymbolAddress((void**)&gx, g_Xh);
    __half* gy;  cudaGetSymbolAddress((void**)&gy, g_Yh);

    cudaFuncSetAttribute(k_gemm_h<0>, cudaFuncAttributeMaxDynamicSharedMemorySize, GEMM_SMEM);
    cudaFuncSetAttribute(k_gemm_h<1>, cudaFuncAttributeMaxDynamicSharedMemorySize, GEMM_SMEM);
    cudaFuncSetAttribute(k_attn, cudaFuncAttributeMaxDynamicSharedMemorySize, ATTN_SMEM);

    k_cvt<<<(B_ * L_ * D_ / 8) / 256, 256>>>((const float4*)x);
    k_transpose<<<dim3(3 * D_ / 32, D_ / 32), dim3(32, 8)>>>(w_qkv, wt1, D_, 3 * D_);
    k_transpose<<<dim3(D_ / 32, D_ / 32), dim3(32, 8)>>>(w_proj, wt2, D_, D_);
    k_gemm_h<0><<<dim3(3 * D_ / 256, B_ * L_ / 128), 256, GEMM_SMEM>>>(gx, wt1, nullptr);
    k_rope<<<(B_ * H_ * L_ * 64) / 256, 256>>>();
    k_attn<<<dim3(16, 32), 256, ATTN_SMEM>>>(amask);
    k_gemm_h<1><<<dim3(D_ / 256, B_ * L_ / 128), 256, GEMM_SMEM>>>(gy, wt2, out);
}

// round 8
// speedup vs baseline: 6.5508x; 1.0009x over previous
#include <cuda_runtime.h>
#include <cuda_fp16.h>
#include <math.h>
#include <stdint.h>

#define B_  2
#define L_  2048
#define D_  2048
#define H_  16
#define DH  128
#define NEGV  (-1000000000.0f)
#define SCALE 0.08838834764831845f

// ---- fp16 GEMM config: CTA 128x256, k-chunk 64 halves (=128B rows) -------
#define KCH 64
#define KTH (D_ / KCH)        // 32
#define RS  72                // smem row stride in halves (144B)
#define A_H (128 * RS)
#define STG_H (384 * RS)
#define STG_B (STG_H * 2)
#define GEMM_SMEM (3 * STG_B)
// ---- attn smem ----
#define RSA 136               // attn row stride in halves (272B)
#define TILE_H (128 * RSA)
#define AT_RED1 (3 * TILE_H * 2)
#define AT_RED2 (AT_RED1 + 2048)
#define AT_AM   (AT_RED2 + 2048)
#define ATTN_SMEM (AT_AM + 512)

// ---------------- scratch (device globals; no runtime allocation) ----------
__device__ __half g_Xh[B_*L_*D_];
__device__ __half g_Qh[B_*H_*L_*DH];          // [B,H,L,Dh] fp16, rope+scale
__device__ __half g_Kh[B_*H_*L_*DH];          // [B,H,L,Dh] fp16, rope
__device__ __half g_Vh[B_*H_*DH*L_];          // [B,H,Dh,L] fp16 (transposed)
__device__ __half g_Yh[B_*L_*D_];
__device__ __half g_WT1h[3*D_*D_];            // fp16(w_qkv^T)
__device__ __half g_WT2h[D_*D_];              // fp16(w_proj^T)

// ---------------------------- helpers -------------------------------------
__device__ __forceinline__ uint32_t smem_u32(const void* p) {
    uint32_t a;
    asm("{ .reg .u64 t; cvta.to.shared.u64 t, %1; cvt.u32.u64 %0, t; }"
        : "=r"(a) : "l"(p));
    return a;
}
__device__ __forceinline__ void cp16(uint32_t s, const void* g) {
    asm volatile("cp.async.cg.shared.global [%0], [%1], 16;\n" :: "r"(s), "l"(g));
}
template<int N> __device__ __forceinline__ void cpwait() {
    asm volatile("cp.async.wait_group %0;\n" :: "n"(N));
}
__device__ __forceinline__ void mma_f16(float* c, const uint32_t* a, const uint32_t* b) {
    asm volatile(
        "mma.sync.aligned.m16n8k16.row.col.f32.f16.f16.f32 "
        "{%0,%1,%2,%3},{%4,%5,%6,%7},{%8,%9},{%0,%1,%2,%3};\n"
        : "+f"(c[0]), "+f"(c[1]), "+f"(c[2]), "+f"(c[3])
        : "r"(a[0]), "r"(a[1]), "r"(a[2]), "r"(a[3]), "r"(b[0]), "r"(b[1]));
}
__device__ __forceinline__ void ldsm4(uint32_t& r0, uint32_t& r1, uint32_t& r2,
                                      uint32_t& r3, uint32_t a) {
    asm volatile("ldmatrix.sync.aligned.m8n8.x4.shared.b16 {%0,%1,%2,%3}, [%4];"
                 : "=r"(r0), "=r"(r1), "=r"(r2), "=r"(r3) : "r"(a));
}
__device__ __forceinline__ uint32_t h2u(__half2 h) {
    return *reinterpret_cast<uint32_t*>(&h);
}

// ============ fp16 GEMM: C[128bm, 256bn] = A[.,2048] @ B^T ================
template<int EPI>
__global__ __launch_bounds__(256, 1) void k_gemm_h(const __half* __restrict__ A,
                                                   const __half* __restrict__ Bw,
                                                   float* __restrict__ out) {
    extern __shared__ __half smh[];
    const int tid = threadIdx.x, lane = tid & 31, warp = tid >> 5;
    const int wm = warp >> 2, wn = warp & 3;
    const int r = lane >> 2, qc = lane & 3;
    const int bn = blockIdx.x, bm = blockIdx.y;

    const int rA = tid >> 3, kg = tid & 7;
    const __half* srcA = A + (size_t)(bm * 128 + rA) * D_ + kg * 8;
    const __half* srcB = Bw + (size_t)(bn * 256 + rA) * D_ + kg * 8;
    const uint32_t sb = smem_u32(smh);
    const uint32_t dA = sb + rA * (RS * 2) + kg * 16;
    const uint32_t dB = sb + A_H * 2 + rA * (RS * 2) + kg * 16;

    const uint32_t aBase = sb + ((wm * 64 + (lane & 15)) * RS + (lane >> 4) * 8) * 2;
    const uint32_t bBase = sb + A_H * 2 +
        ((wn * 64 + (lane >> 4) * 8 + (lane & 7)) * RS + ((lane >> 3) & 1) * 8) * 2;

    float acc[4][8][4];
#pragma unroll
    for (int i = 0; i < 4; i++)
#pragma unroll
        for (int j = 0; j < 8; j++)
#pragma unroll
            for (int k = 0; k < 4; k++) acc[i][j][k] = 0.f;

#define ISSUE(cc)                                                             \
    { const uint32_t so_ = ((cc) % 3) * STG_B;                                \
      const int ko_ = (cc) * KCH;                                             \
      _Pragma("unroll") for (int i_ = 0; i_ < 4; i_++)                        \
          cp16(dA + so_ + i_ * (32 * RS * 2), srcA + ko_ + (size_t)i_ * 32 * D_); \
      _Pragma("unroll") for (int i_ = 0; i_ < 8; i_++)                        \
          cp16(dB + so_ + i_ * (32 * RS * 2), srcB + ko_ + (size_t)i_ * 32 * D_); \
      asm volatile("cp.async.commit_group;\n" ::: "memory"); }

#define LOADF(buf, k0)                                                        \
    { _Pragma("unroll") for (int mi_ = 0; mi_ < 4; mi_++)                     \
          ldsm4(af[buf][mi_][0], af[buf][mi_][1], af[buf][mi_][2],            \
                af[buf][mi_][3], aBase + so + (mi_ * 16 * RS + (k0)) * 2);    \
      _Pragma("unroll") for (int p_ = 0; p_ < 4; p_++)                        \
          ldsm4(bf[buf][2*p_][0], bf[buf][2*p_][1], bf[buf][2*p_+1][0],       \
                bf[buf][2*p_+1][1], bBase + so + (p_ * 16 * RS + (k0)) * 2); }

    ISSUE(0); ISSUE(1);

    for (int ct = 0; ct < KTH; ct++) {
        if (ct < KTH - 1) cpwait<1>(); else cpwait<0>();
        __syncthreads();
        if (ct + 2 < KTH) ISSUE(ct + 2);   // stage (ct+2)%3 free after this sync
        const uint32_t so = (ct % 3) * STG_B;
        uint32_t af[2][4][4], bf[2][8][2];
        LOADF(0, 0);
#pragma unroll
        for (int ks = 0; ks < 4; ks++) {
            const int cur = ks & 1;
            if (ks < 3) LOADF(cur ^ 1, (ks + 1) * 16);
#pragma unroll
            for (int mi = 0; mi < 4; mi++)
#pragma unroll
                for (int ni = 0; ni < 8; ni++)
                    mma_f16(acc[mi][ni], af[cur][mi], bf[cur][ni]);
        }
    }
#undef ISSUE
#undef LOADF

    // ---- epilogue ----
#pragma unroll
    for (int mi = 0; mi < 4; mi++)
#pragma unroll
        for (int ni = 0; ni < 8; ni++)
#pragma unroll
            for (int rg = 0; rg < 4; rg++) {
                int row = wm * 64 + mi * 16 + r + ((rg >> 1) ? 8 : 0);
                int col = wn * 64 + ni * 8 + 2 * qc + (rg & 1);
                int m = bm * 128 + row, n = bn * 256 + col;
                float v = acc[mi][ni][rg];
                if (EPI == 1) {
                    out[(size_t)m * D_ + n] = v;
                } else {
                    int bb = m >> 11, l = m & 2047;
                    int part = n >> 11, idx = n & 2047;
                    int h = idx >> 7, d = idx & 127;
                    __half hv = __float2half_rn(v);
                    if (part == 2)
                        g_Vh[(((size_t)bb * H_ + h) * DH + d) * L_ + l] = hv;
                    else if (part == 1)
                        g_Kh[(((size_t)bb * H_ + h) * L_ + l) * DH + d] = hv;
                    else
                        g_Qh[(((size_t)bb * H_ + h) * L_ + l) * DH + d] = hv;
                }
            }
}

// -------------------- x -> fp16 convert ------------------------------------
__global__ __launch_bounds__(256) void k_cvt(const float4* __restrict__ src) {
    int i = blockIdx.x * 256 + threadIdx.x;
    float4 a = src[2 * i], b = src[2 * i + 1];
    uint4 o;
    o.x = h2u(__floats2half2_rn(a.x, a.y));
    o.y = h2u(__floats2half2_rn(a.z, a.w));
    o.z = h2u(__floats2half2_rn(b.x, b.y));
    o.w = h2u(__floats2half2_rn(b.z, b.w));
    ((uint4*)g_Xh)[i] = o;
}

// ----------------- weight transpose (+ fp16 convert) -----------------------
__global__ __launch_bounds__(256) void k_transpose(const float* __restrict__ src,
                                                   __half* __restrict__ dst,
                                                   int R, int C) {
    __shared__ float t[32][33];
    int bx = blockIdx.x * 32, by = blockIdx.y * 32;
    int x = bx + threadIdx.x;
#pragma unroll
    for (int i = 0; i < 32; i += 8)
        t[threadIdx.y + i][threadIdx.x] = src[(size_t)(by + threadIdx.y + i) * C + x];
    __syncthreads();
    int x2 = by + threadIdx.x;
#pragma unroll
    for (int i = 0; i < 32; i += 8)
        dst[(size_t)(bx + threadIdx.y + i) * R + x2] =
            __float2half_rn(t[threadIdx.x][threadIdx.y + i]);
}

// ==== RoPE on Q (folds SCALE) and K, in place, fp16 in/out ================
__global__ void k_rope() {
    int idx = blockIdx.x * blockDim.x + threadIdx.x;
    int i   = idx & 63;
    int bhl = idx >> 6;
    int l   = bhl & 2047;
    float inv_freq = powf(10000.0f, -(float)(2 * i) * (1.0f / 128.0f));
    float ang = (float)l * inv_freq;
    float s, cc;
    sincosf(ang, &s, &cc);
    int base = bhl << 7;
    float q0 = __half2float(g_Qh[base + i]), q1 = __half2float(g_Qh[base + i + 64]);
    g_Qh[base + i]      = __float2half_rn((q0 * cc - q1 * s) * SCALE);
    g_Qh[base + i + 64] = __float2half_rn((q1 * cc + q0 * s) * SCALE);
    float k0 = __half2float(g_Kh[base + i]), k1 = __half2float(g_Kh[base + i + 64]);
    g_Kh[base + i]      = __float2half_rn(k0 * cc - k1 * s);
    g_Kh[base + i + 64] = __float2half_rn(k1 * cc + k0 * s);
}

// ======== fused flash attention (fp16 mma + ldmatrix + frag pipeline) =====
__global__ __launch_bounds__(256, 1) void k_attn(const int* __restrict__ amask) {
    extern __shared__ __half smh[];
    __half* Qs = smh;
    __half* Ks = smh + TILE_H;            // reused as Ps
    __half* Vs = smh + 2 * TILE_H;
    float* red1 = (float*)((char*)smh + AT_RED1);
    float* red2 = (float*)((char*)smh + AT_RED2);
    int*   am_s = (int*)((char*)smh + AT_AM);

    const int bm = 15 - blockIdx.x;
    const int bh = blockIdx.y;
    const int bb = bh >> 4, hh = bh & 15;
    const int tid = threadIdx.x;
    const int lane = tid & 31, warp = tid >> 5;
    const int wm = warp >> 2, wn = warp & 3;
    const int r = lane >> 2, qc = lane & 3;

    const uint32_t usb = smem_u32(smh);
    const uint32_t aOff = ((wm * 64 + (lane & 15)) * RSA + (lane >> 4) * 8) * 2;
    const uint32_t bOff = ((wn * 32 + (lane >> 4) * 8 + (lane & 7)) * RSA +
                           ((lane >> 3) & 1) * 8) * 2;
    const uint32_t qA = usb + aOff;
    const uint32_t kB = usb + TILE_H * 2 + bOff;
    const uint32_t pA = usb + TILE_H * 2 + aOff;
    const uint32_t vB = usb + 2 * TILE_H * 2 + bOff;

#define LOADQK(buf, k0)                                                       \
    { _Pragma("unroll") for (int mi_ = 0; mi_ < 4; mi_++)                     \
          ldsm4(af[buf][mi_][0], af[buf][mi_][1], af[buf][mi_][2],            \
                af[buf][mi_][3], qA + (mi_ * 16 * RSA + (k0)) * 2);           \
      _Pragma("unroll") for (int p_ = 0; p_ < 2; p_++)                        \
          ldsm4(bf[buf][2*p_][0], bf[buf][2*p_][1], bf[buf][2*p_+1][0],       \
                bf[buf][2*p_+1][1], kB + (p_ * 16 * RSA + (k0)) * 2); }
#define LOADPV(buf, k0)                                                       \
    { _Pragma("unroll") for (int mi_ = 0; mi_ < 4; mi_++)                     \
          ldsm4(af[buf][mi_][0], af[buf][mi_][1], af[buf][mi_][2],            \
                af[buf][mi_][3], pA + (mi_ * 16 * RSA + (k0)) * 2);           \
      _Pragma("unroll") for (int p_ = 0; p_ < 2; p_++)                        \
          ldsm4(bf[buf][2*p_][0], bf[buf][2*p_][1], bf[buf][2*p_+1][0],       \
                bf[buf][2*p_+1][1], vB + (p_ * 16 * RSA + (k0)) * 2); }

    // --- load Q block (already scaled+roped fp16) ---
    const __half* Qg = g_Qh + (size_t)bh * L_ * DH + (size_t)bm * 128 * DH;
#pragma unroll
    for (int i = 0; i < 8; i++) {
        int g = i * 256 + tid;
        int row = g >> 4, kgg = g & 15;
        *(uint4*)&Qs[row * RSA + kgg * 8] = *(const uint4*)(Qg + row * DH + kgg * 8);
    }

    float oacc[4][4][4];
#pragma unroll
    for (int _i = 0; _i < 4; _i++)
#pragma unroll
        for (int _j = 0; _j < 4; _j++)
#pragma unroll
            for (int _k = 0; _k < 4; _k++) oacc[_i][_j][_k] = 0.f;
    float mrow[4][2], lrow[4][2];
#pragma unroll
    for (int mi = 0; mi < 4; mi++)
#pragma unroll
        for (int h = 0; h < 2; h++) { mrow[mi][h] = -3.0e38f; lrow[mi][h] = 0.f; }

    for (int kb = 0; kb <= bm; kb++) {
        __syncthreads();
        const __half* Kg = g_Kh + (size_t)bh * L_ * DH + (size_t)kb * 128 * DH;
        const __half* Vg = g_Vh + (size_t)bh * DH * L_ + (size_t)kb * 128;
#pragma unroll
        for (int i = 0; i < 8; i++) {
            int g = i * 256 + tid;
            int row = g >> 4, kgg = g & 15;
            *(uint4*)&Ks[row * RSA + kgg * 8] = *(const uint4*)(Kg + row * DH + kgg * 8);
            *(uint4*)&Vs[row * RSA + kgg * 8] = *(const uint4*)(Vg + (size_t)row * L_ + kgg * 8);
        }
        if (tid < 128) am_s[tid] = amask[bb * L_ + kb * 128 + tid];
        __syncthreads();

        // --- S = Q @ K^T (frag ping-pong) ---
        float sacc[4][4][4];
#pragma unroll
        for (int _i = 0; _i < 4; _i++)
#pragma unroll
            for (int _j = 0; _j < 4; _j++)
#pragma unroll
                for (int _k = 0; _k < 4; _k++) sacc[_i][_j][_k] = 0.f;
        {
            uint32_t af[2][4][4], bf[2][4][2];
            LOADQK(0, 0);
#pragma unroll
            for (int ks = 0; ks < 8; ks++) {
                const int cur = ks & 1;
                if (ks < 7) LOADQK(cur ^ 1, (ks + 1) * 16);
#pragma unroll
                for (int mi = 0; mi < 4; mi++)
#pragma unroll
                    for (int ni = 0; ni < 4; ni++)
                        mma_f16(sacc[mi][ni], af[cur][mi], bf[cur][ni]);
            }
        }

        // --- mask ---
        int amf[4][2];
#pragma unroll
        for (int ni = 0; ni < 4; ni++)
#pragma unroll
            for (int par = 0; par < 2; par++)
                amf[ni][par] = am_s[wn * 32 + ni * 8 + 2 * qc + par];
        const bool diag = (kb == bm);
#pragma unroll
        for (int mi = 0; mi < 4; mi++)
#pragma unroll
            for (int ni = 0; ni < 4; ni++)
#pragma unroll
                for (int rg = 0; rg < 4; rg++) {
                    bool ok = amf[ni][rg & 1] != 0;
                    if (diag) {
                        int qr = bm * 128 + wm * 64 + mi * 16 + r + ((rg >> 1) ? 8 : 0);
                        int kc2 = kb * 128 + wn * 32 + ni * 8 + 2 * qc + (rg & 1);
                        ok = ok && (kc2 <= qr);
                    }
                    if (!ok) sacc[mi][ni][rg] = NEGV;
                }

        // --- rowmax ---
#pragma unroll
        for (int mi = 0; mi < 4; mi++)
#pragma unroll
            for (int h = 0; h < 2; h++) {
                float pm = -3.0e38f;
#pragma unroll
                for (int ni = 0; ni < 4; ni++)
                    pm = fmaxf(pm, fmaxf(sacc[mi][ni][2 * h], sacc[mi][ni][2 * h + 1]));
                pm = fmaxf(pm, __shfl_xor_sync(0xffffffff, pm, 1));
                pm = fmaxf(pm, __shfl_xor_sync(0xffffffff, pm, 2));
                if (qc == 0)
                    red1[(wm * 64 + mi * 16 + r + 8 * h) * 4 + wn] = pm;
            }
        __syncthreads();

        float mnew[4][2], sfac[4][2];
#pragma unroll
        for (int mi = 0; mi < 4; mi++)
#pragma unroll
            for (int h = 0; h < 2; h++) {
                int row = wm * 64 + mi * 16 + r + 8 * h;
                float mb = fmaxf(fmaxf(red1[row * 4 + 0], red1[row * 4 + 1]),
                                 fmaxf(red1[row * 4 + 2], red1[row * 4 + 3]));
                float mn = fmaxf(mrow[mi][h], mb);
                sfac[mi][h] = __expf(mrow[mi][h] - mn);
                mnew[mi][h] = mn;
                mrow[mi][h] = mn;
            }

        // --- exp, partial sums, rescale O, store P (half) into Ks ---
#pragma unroll
        for (int mi = 0; mi < 4; mi++)
#pragma unroll
            for (int h = 0; h < 2; h++) {
                float ps = 0.f;
#pragma unroll
                for (int ni = 0; ni < 4; ni++) {
                    float p0 = __expf(sacc[mi][ni][2 * h]     - mnew[mi][h]);
                    float p1 = __expf(sacc[mi][ni][2 * h + 1] - mnew[mi][h]);
                    sacc[mi][ni][2 * h]     = p0;
                    sacc[mi][ni][2 * h + 1] = p1;
                    ps += p0 + p1;
                    oacc[mi][ni][2 * h]     *= sfac[mi][h];
                    oacc[mi][ni][2 * h + 1] *= sfac[mi][h];
                }
                ps += __shfl_xor_sync(0xffffffff, ps, 1);
                ps += __shfl_xor_sync(0xffffffff, ps, 2);
                int row = wm * 64 + mi * 16 + r + 8 * h;
                if (qc == 0) red2[row * 4 + wn] = ps;
                lrow[mi][h] *= sfac[mi][h];
#pragma unroll
                for (int ni = 0; ni < 4; ni++)
                    *(__half2*)&Ks[row * RSA + wn * 32 + ni * 8 + 2 * qc] =
                        __floats2half2_rn(sacc[mi][ni][2 * h], sacc[mi][ni][2 * h + 1]);
            }
        __syncthreads();

#pragma unroll
        for (int mi = 0; mi < 4; mi++)
#pragma unroll
            for (int h = 0; h < 2; h++) {
                int row = wm * 64 + mi * 16 + r + 8 * h;
                lrow[mi][h] += red2[row * 4 + 0] + red2[row * 4 + 1] +
                               red2[row * 4 + 2] + red2[row * 4 + 3];
            }

        // --- O += P @ V (frag ping-pong) ---
        {
            uint32_t af[2][4][4], bf[2][4][2];
            LOADPV(0, 0);
#pragma unroll
            for (int ks = 0; ks < 8; ks++) {
                const int cur = ks & 1;
                if (ks < 7) LOADPV(cur ^ 1, (ks + 1) * 16);
#pragma unroll
                for (int mi = 0; mi < 4; mi++)
#pragma unroll
                    for (int ni = 0; ni < 4; ni++)
                        mma_f16(oacc[mi][ni], af[cur][mi], bf[cur][ni]);
            }
        }
    }
#undef LOADQK
#undef LOADPV

    // --- epilogue: O /= l, write half to g_Yh ---
#pragma unroll
    for (int mi = 0; mi < 4; mi++)
#pragma unroll
        for (int h = 0; h < 2; h++) {
            float inv = 1.0f / lrow[mi][h];
            int qg = bm * 128 + wm * 64 + mi * 16 + r + 8 * h;
#pragma unroll
            for (int ni = 0; ni < 4; ni++) {
                int col = hh * DH + wn * 32 + ni * 8 + 2 * qc;
                *(__half2*)&g_Yh[(size_t)(bb * L_ + qg) * D_ + col] =
                    __floats2half2_rn(oacc[mi][ni][2 * h] * inv,
                                      oacc[mi][ni][2 * h + 1] * inv);
            }
        }
}

// ============================== launcher ==================================
extern "C" void kernel_launch(void* const* d_in, const int* in_sizes, int n_in,
                              void* d_out, int out_size) {
    const float* x      = (const float*)d_in[0];
    const int*   amask  = (const int*)d_in[1];
    const float* w_qkv  = (const float*)d_in[2];
    const float* w_proj = (const float*)d_in[3];
    float* out = (float*)d_out;

    __half* wt1; cudaGetSymbolAddress((void**)&wt1, g_WT1h);
    __half* wt2; cudaGetSymbolAddress((void**)&wt2, g_WT2h);
    __half* gx;  cudaGetSymbolAddress((void**)&gx, g_Xh);
    __half* gy;  cudaGetSymbolAddress((void**)&gy, g_Yh);

    cudaFuncSetAttribute(k_gemm_h<0>, cudaFuncAttributeMaxDynamicSharedMemorySize, GEMM_SMEM);
    cudaFuncSetAttribute(k_gemm_h<1>, cudaFuncAttributeMaxDynamicSharedMemorySize, GEMM_SMEM);
    cudaFuncSetAttribute(k_attn, cudaFuncAttributeMaxDynamicSharedMemorySize, ATTN_SMEM);

    k_cvt<<<(B_ * L_ * D_ / 8) / 256, 256>>>((const float4*)x);
    k_transpose<<<dim3(3 * D_ / 32, D_ / 32), dim3(32, 8)>>>(w_qkv, wt1, D_, 3 * D_);
    k_transpose<<<dim3(D_ / 32, D_ / 32), dim3(32, 8)>>>(w_proj, wt2, D_, D_);
    k_gemm_h<0><<<dim3(3 * D_ / 256, B_ * L_ / 128), 256, GEMM_SMEM>>>(gx, wt1, nullptr);
    k_rope<<<(B_ * H_ * L_ * 64) / 256, 256>>>();
    k_attn<<<dim3(16, 32), 256, ATTN_SMEM>>>(amask);
    k_gemm_h<1><<<dim3(D_ / 256, B_ * L_ / 128), 256, GEMM_SMEM>>>(gy, wt2, out);
}